// round 2
// baseline (speedup 1.0000x reference)
#include <cuda_runtime.h>

#define N_NODES 2000
#define N_EDGES 32000
#define NG      320      // B*T graphs
#define OUTF    8
#define HID     24
#define BB      16
#define TT      20
#define NEG_SLOPE 0.2f

// ---------------- scratch (device globals; no allocs allowed) ----------------
__device__ float  g_wT[(size_t)N_EDGES * NG];   // [E][320]
__device__ float  g_xT[(size_t)N_NODES * NG];   // [N][320]
__device__ int2   g_col[N_EDGES];               // CSR payload: (src, orig edge id)
__device__ int    g_rowptr[N_NODES + 1];
__device__ int    g_deg[N_NODES];               // zero at replay start (scan re-zeroes)
__device__ int    g_cur[N_NODES];               // zero at replay start (gat re-zeroes)
__device__ float2 g_S[NG];                      // per-graph (S1, S2); scan zeroes

// =====================================================================
// K1: fused transposes + degree histogram
//   grid = (1000, 20): y<10 -> w transpose tiles; y>=10 -> x transpose tiles
//   hist piggybacks on blocks (y==0, x<125)
// =====================================================================
__global__ void prep_kernel(const float* __restrict__ xin,
                            const float* __restrict__ win,
                            const int* __restrict__ dst) {
    __shared__ float tile[32][33];
    int tx = threadIdx.x, ty = threadIdx.y;  // 32 x 8

    if (blockIdx.y < 10) {
        // ---- edge-weight transpose [320][E] -> [E][320] ----
        int cb = blockIdx.x * 32;            // edge base
        int rb = blockIdx.y * 32;            // graph base
        #pragma unroll
        for (int i = 0; i < 32; i += 8)
            tile[ty + i][tx] = win[(size_t)(rb + ty + i) * N_EDGES + cb + tx];
        __syncthreads();
        #pragma unroll
        for (int i = 0; i < 32; i += 8)
            g_wT[(size_t)(cb + ty + i) * NG + rb + tx] = tile[tx][ty + i];

        // ---- degree histogram (first 125 blocks of y==0) ----
        if (blockIdx.y == 0 && blockIdx.x < 125) {
            int e = blockIdx.x * 256 + ty * 32 + tx;
            if (e < N_EDGES) atomicAdd(&g_deg[dst[e]], 1);
        }
    } else {
        // ---- node-feature transpose [320][N] -> [N][320] ----
        if (blockIdx.x >= 63) return;
        int cb = blockIdx.x * 32;            // node base
        int rb = (blockIdx.y - 10) * 32;     // graph base
        #pragma unroll
        for (int i = 0; i < 32; i += 8) {
            int c = cb + tx;
            tile[ty + i][tx] = (c < N_NODES)
                ? xin[(size_t)(rb + ty + i) * N_NODES + c] : 0.0f;
        }
        __syncthreads();
        #pragma unroll
        for (int i = 0; i < 32; i += 8) {
            int c = cb + ty + i;
            if (c < N_NODES) g_xT[(size_t)c * NG + rb + tx] = tile[tx][ty + i];
        }
    }
}

// =====================================================================
// K2: scan (deg -> rowptr), then recycle state: zero deg (for next replay)
//     and zero g_S (consumed by gat this replay)
// =====================================================================
__global__ void scan_kernel() {
    __shared__ int sh[1024];
    int t = threadIdx.x;
    int a = (2 * t     < N_NODES) ? g_deg[2 * t]     : 0;
    int b = (2 * t + 1 < N_NODES) ? g_deg[2 * t + 1] : 0;
    int v = a + b;
    sh[t] = v;
    __syncthreads();
    for (int off = 1; off < 1024; off <<= 1) {
        int add = (t >= off) ? sh[t - off] : 0;
        __syncthreads();
        sh[t] += add;
        __syncthreads();
    }
    int incl = sh[t];
    int excl = incl - v;
    if (2 * t     < N_NODES) { g_rowptr[2 * t]     = excl;     g_deg[2 * t]     = 0; }
    if (2 * t + 1 < N_NODES) { g_rowptr[2 * t + 1] = excl + a; g_deg[2 * t + 1] = 0; }
    if (t == 1023) g_rowptr[N_NODES] = incl;
    if (t < NG) g_S[t] = make_float2(0.0f, 0.0f);
}

// =====================================================================
// K3: scatter edges into CSR order
// =====================================================================
__global__ void scatter_kernel(const int* __restrict__ src, const int* __restrict__ dst) {
    int e = blockIdx.x * blockDim.x + threadIdx.x;
    if (e < N_EDGES) {
        int d = dst[e];
        int pos = g_rowptr[d] + atomicAdd(&g_cur[d], 1);
        g_col[pos] = make_int2(src[e], e);
    }
}

// =====================================================================
// K4: GAT reduction. warp = (node, group of 64 graphs); lane owns 2 graphs
//     via float2 (two independent accumulator chains -> 2x MLP).
//     Single pass: den += e^v; T1 += e^v*xs; T2 += e^v*w; node contributes
//     T1/den, T2/den to the per-graph sums. Also re-zeroes g_cur.
// =====================================================================
__global__ void gat_kernel(const float* __restrict__ W_node,
                           const float* __restrict__ W_edge,
                           const float* __restrict__ attn_l,
                           const float* __restrict__ attn_e,
                           const float* __restrict__ attn_r) {
    int gid  = blockIdx.x * blockDim.x + threadIdx.x;
    if (gid < N_NODES) g_cur[gid] = 0;        // recycle for next replay

    int warp = gid >> 5;
    int lane = threadIdx.x & 31;
    if (warp >= N_NODES * (NG / 64)) return;
    int node  = warp / (NG / 64);
    int gg    = warp % (NG / 64);
    int gbase = gg * 64 + lane * 2;

    float cL = 0.f, cE = 0.f, cR = 0.f;
    #pragma unroll
    for (int o = 0; o < OUTF; o++) {
        float wn = __ldg(&W_node[o]);
        float we = __ldg(&W_edge[o]);
        cL = fmaf(wn, __ldg(&attn_l[o]), cL);
        cR = fmaf(wn, __ldg(&attn_r[o]), cR);
        cE = fmaf(we, __ldg(&attn_e[o]), cE);
    }

    float2 xd = *(const float2*)&g_xT[(size_t)node * NG + gbase];
    float bd0 = cR * xd.x, bd1 = cR * xd.y;
    int s0 = g_rowptr[node], s1 = g_rowptr[node + 1];

    float den0 = 0.f, T10 = 0.f, T20 = 0.f;
    float den1 = 0.f, T11 = 0.f, T21 = 0.f;
    #pragma unroll 2
    for (int j = s0; j < s1; j++) {
        int2 se = g_col[j];
        float2 w2 = *(const float2*)&g_wT[(size_t)se.y * NG + gbase];
        float2 x2 = *(const float2*)&g_xT[(size_t)se.x * NG + gbase];
        float v0 = fmaf(cL, x2.x, fmaf(cE, w2.x, bd0));
        float v1 = fmaf(cL, x2.y, fmaf(cE, w2.y, bd1));
        v0 = (v0 > 0.f) ? v0 : NEG_SLOPE * v0;
        v1 = (v1 > 0.f) ? v1 : NEG_SLOPE * v1;
        float p0 = __expf(v0);
        float p1 = __expf(v1);
        den0 += p0;  T10 = fmaf(p0, x2.x, T10);  T20 = fmaf(p0, w2.x, T20);
        den1 += p1;  T11 = fmaf(p1, x2.y, T11);  T21 = fmaf(p1, w2.y, T21);
    }
    if (s1 > s0) {
        float i0 = 1.0f / den0, i1 = 1.0f / den1;
        atomicAdd(&g_S[gbase].x,     T10 * i0);
        atomicAdd(&g_S[gbase].y,     T20 * i0);
        atomicAdd(&g_S[gbase + 1].x, T11 * i1);
        atomicAdd(&g_S[gbase + 1].y, T21 * i1);
    }
}

// =====================================================================
// K5: fused LSTM + fc + fcc. One CTA per batch element; hs stays in smem.
// =====================================================================
__device__ __forceinline__ float sigm(float x) { return 1.0f / (1.0f + __expf(-x)); }

__global__ void lstm_head_kernel(const float* __restrict__ W_node,
                                 const float* __restrict__ W_edge,
                                 const float* __restrict__ gat_b,
                                 const float* __restrict__ w_ih,
                                 const float* __restrict__ w_hh,
                                 const float* __restrict__ b_ih,
                                 const float* __restrict__ b_hh,
                                 const float* __restrict__ fc_w,
                                 const float* __restrict__ fc_b,
                                 const float* __restrict__ fcc_w,
                                 const float* __restrict__ fcc_b,
                                 float* __restrict__ out) {
    int b = blockIdx.x;          // 0..15
    int tid = threadIdx.x;       // 128 threads
    __shared__ float h[HID], c[HID], gates[4 * HID], xt[OUTF];
    __shared__ float hs[TT][HID];          // all hidden states
    __shared__ float fcv[TT * 160];        // fc outputs for all 20 rows

    float wih[OUTF];
    float whh[HID];
    float bsum = 0.f;
    if (tid < 4 * HID) {
        #pragma unroll
        for (int k = 0; k < OUTF; k++) wih[k] = w_ih[tid * OUTF + k];
        #pragma unroll
        for (int j = 0; j < HID; j++) whh[j] = w_hh[tid * HID + j];
        bsum = b_ih[tid] + b_hh[tid];
    }
    if (tid < HID) { h[tid] = 0.f; c[tid] = 0.f; }
    __syncthreads();

    for (int t = 0; t < TT; t++) {
        if (tid < OUTF) {
            float2 S = g_S[b * TT + t];
            xt[tid] = fmaf(S.x, W_node[tid], S.y * W_edge[tid]) * (1.0f / N_NODES)
                      + gat_b[tid];
        }
        __syncthreads();
        if (tid < 4 * HID) {
            float acc = bsum;
            #pragma unroll
            for (int k = 0; k < OUTF; k++) acc = fmaf(wih[k], xt[k], acc);
            #pragma unroll
            for (int j = 0; j < HID; j++) acc = fmaf(whh[j], h[j], acc);
            gates[tid] = acc;
        }
        __syncthreads();
        if (tid < HID) {
            float gi = sigm(gates[tid]);
            float gf = sigm(gates[HID + tid]);
            float gc = tanhf(gates[2 * HID + tid]);
            float go = sigm(gates[3 * HID + tid]);
            float cn = fmaf(gf, c[tid], gi * gc);
            c[tid] = cn;
            float hn = go * tanhf(cn);
            h[tid] = hn;
            hs[t][tid] = hn;
        }
        __syncthreads();
    }

    // fc: 20 rows x 160 outputs, dot over 24
    for (int idx = tid; idx < TT * 160; idx += 128) {
        int r = idx / 160, m = idx % 160;
        float acc = fc_b[m];
        #pragma unroll
        for (int k = 0; k < HID; k++) acc = fmaf(hs[r][k], fc_w[m * HID + k], acc);
        fcv[idx] = acc;
    }
    __syncthreads();

    // fcc: 20 rows x 20 outputs, dot over 160
    for (int idx = tid; idx < TT * 20; idx += 128) {
        int r = idx / 20, m = idx % 20;
        const float* fv = &fcv[r * 160];
        float acc = fcc_b[m];
        #pragma unroll 8
        for (int q = 0; q < 160; q++) acc = fmaf(fv[q], fcc_w[m * 160 + q], acc);
        out[(b * TT + r) * 20 + m] = acc;
    }
}

// ---------------- launch ----------------
extern "C" void kernel_launch(void* const* d_in, const int* in_sizes, int n_in,
                              void* d_out, int out_size) {
    const float* x      = (const float*)d_in[0];
    const float* ew     = (const float*)d_in[1];
    const int*   src    = (const int*)  d_in[2];
    const int*   dst    = (const int*)  d_in[3];
    const float* W_node = (const float*)d_in[4];
    const float* W_edge = (const float*)d_in[5];
    const float* attn_l = (const float*)d_in[6];
    const float* attn_e = (const float*)d_in[7];
    const float* attn_r = (const float*)d_in[8];
    const float* gat_b  = (const float*)d_in[9];
    const float* w_ih   = (const float*)d_in[10];
    const float* w_hh   = (const float*)d_in[11];
    const float* b_ih   = (const float*)d_in[12];
    const float* b_hh   = (const float*)d_in[13];
    const float* fc_w   = (const float*)d_in[14];
    const float* fc_b   = (const float*)d_in[15];
    const float* fcc_w  = (const float*)d_in[16];
    const float* fcc_b  = (const float*)d_in[17];
    float* out = (float*)d_out;

    prep_kernel<<<dim3(1000, 20), dim3(32, 8)>>>(x, ew, dst);
    scan_kernel<<<1, 1024>>>();
    scatter_kernel<<<(N_EDGES + 255) / 256, 256>>>(src, dst);
    // 2000 nodes * 5 graph-groups(64) = 10000 warps; 8 warps/CTA -> 1250 CTAs
    gat_kernel<<<1250, 256>>>(W_node, W_edge, attn_l, attn_e, attn_r);
    lstm_head_kernel<<<BB, 128>>>(W_node, W_edge, gat_b, w_ih, w_hh, b_ih, b_hh,
                                  fc_w, fc_b, fcc_w, fcc_b, out);
}

// round 4
// speedup vs baseline: 1.3479x; 1.3479x over previous
#include <cuda_runtime.h>

#define N_NODES 2000
#define N_EDGES 32000
#define NG      320      // B*T graphs
#define OUTF    8
#define HID     24
#define BB      16
#define TT      20
#define NEG_SLOPE 0.2f

// ---------------- scratch (device globals; no allocs allowed) ----------------
__device__ float  g_wT[(size_t)N_EDGES * NG];   // [E][320]
__device__ float  g_xT[(size_t)N_NODES * NG];   // [N][320]
__device__ int2   g_col[N_EDGES];               // CSR payload: (src, orig edge id)
__device__ int    g_rowptr[N_NODES + 1];
__device__ int    g_deg[N_NODES];               // re-zeroed by scan for next replay
__device__ int    g_cur[N_NODES];               // re-zeroed by gat for next replay
__device__ float2 g_S[NG];                      // per-graph (S1, S2); zeroed by scan

// =====================================================================
// K1: fused transposes + degree histogram (packed 1D grid, 256 thr)
//   blocks [0, 10000)      : w transpose tiles (1000 x-tiles x 10 g-tiles)
//   blocks [10000, 10630)  : x transpose tiles (63 x-tiles x 10 g-tiles)
//   blocks [10630, 10755)  : degree histogram (125 blocks)
// =====================================================================
__global__ void prep_kernel(const float* __restrict__ xin,
                            const float* __restrict__ win,
                            const int* __restrict__ dst) {
    __shared__ float tile[32][33];
    int bid = blockIdx.x;
    int tx = threadIdx.x & 31, ty = threadIdx.x >> 5;  // 32 x 8

    if (bid < 10000) {
        int cb = (bid % 1000) * 32;          // edge base
        int rb = (bid / 1000) * 32;          // graph base
        #pragma unroll
        for (int i = 0; i < 32; i += 8)
            tile[ty + i][tx] = win[(size_t)(rb + ty + i) * N_EDGES + cb + tx];
        __syncthreads();
        #pragma unroll
        for (int i = 0; i < 32; i += 8)
            g_wT[(size_t)(cb + ty + i) * NG + rb + tx] = tile[tx][ty + i];
    } else if (bid < 10630) {
        int t = bid - 10000;
        int cb = (t % 63) * 32;              // node base
        int rb = (t / 63) * 32;              // graph base
        #pragma unroll
        for (int i = 0; i < 32; i += 8) {
            int c = cb + tx;
            tile[ty + i][tx] = (c < N_NODES)
                ? xin[(size_t)(rb + ty + i) * N_NODES + c] : 0.0f;
        }
        __syncthreads();
        #pragma unroll
        for (int i = 0; i < 32; i += 8) {
            int c = cb + ty + i;
            if (c < N_NODES) g_xT[(size_t)c * NG + rb + tx] = tile[tx][ty + i];
        }
    } else {
        int e = (bid - 10630) * 256 + threadIdx.x;
        if (e < N_EDGES) atomicAdd(&g_deg[dst[e]], 1);
    }
}

// =====================================================================
// K2: scan (deg -> rowptr); recycles g_deg (next replay) and zeroes g_S
// =====================================================================
__global__ void scan_kernel() {
    __shared__ int sh[1024];
    int t = threadIdx.x;
    int a = (2 * t     < N_NODES) ? g_deg[2 * t]     : 0;
    int b = (2 * t + 1 < N_NODES) ? g_deg[2 * t + 1] : 0;
    int v = a + b;
    sh[t] = v;
    __syncthreads();
    for (int off = 1; off < 1024; off <<= 1) {
        int add = (t >= off) ? sh[t - off] : 0;
        __syncthreads();
        sh[t] += add;
        __syncthreads();
    }
    int incl = sh[t];
    int excl = incl - v;
    if (2 * t     < N_NODES) { g_rowptr[2 * t]     = excl;     g_deg[2 * t]     = 0; }
    if (2 * t + 1 < N_NODES) { g_rowptr[2 * t + 1] = excl + a; g_deg[2 * t + 1] = 0; }
    if (t == 1023) g_rowptr[N_NODES] = incl;
    if (t < NG) g_S[t] = make_float2(0.0f, 0.0f);
}

// =====================================================================
// K3: scatter edges into CSR order
// =====================================================================
__global__ void scatter_kernel(const int* __restrict__ src, const int* __restrict__ dst) {
    int e = blockIdx.x * blockDim.x + threadIdx.x;
    if (e < N_EDGES) {
        int d = dst[e];
        int pos = g_rowptr[d] + atomicAdd(&g_cur[d], 1);
        g_col[pos] = make_int2(src[e], e);
    }
}

// =====================================================================
// K4: GAT reduction. CTA = node (2000 CTAs, 320 threads), thread = graph.
//   Edge records are warp-broadcast; data loads are coalesced across the
//   warp (consecutive graphs). Manual 4x batching -> >=8 independent LDGs
//   in flight per thread. Single pass per edge (no softmax-max needed;
//   logits are O(0.1), exp is safe): den += p; T1 += p*xs; T2 += p*w.
// =====================================================================
__global__ void __launch_bounds__(NG) gat_kernel(const float* __restrict__ W_node,
                           const float* __restrict__ W_edge,
                           const float* __restrict__ attn_l,
                           const float* __restrict__ attn_e,
                           const float* __restrict__ attn_r) {
    int node = blockIdx.x;
    int g = threadIdx.x;                     // graph 0..319
    if (g == 0) g_cur[node] = 0;             // recycle for next replay

    float cL = 0.f, cE = 0.f, cR = 0.f;
    #pragma unroll
    for (int o = 0; o < OUTF; o++) {
        float wn = __ldg(&W_node[o]);
        float we = __ldg(&W_edge[o]);
        cL = fmaf(wn, __ldg(&attn_l[o]), cL);
        cR = fmaf(wn, __ldg(&attn_r[o]), cR);
        cE = fmaf(we, __ldg(&attn_e[o]), cE);
    }

    float xd = g_xT[(size_t)node * NG + g];
    float based = cR * xd;
    int s0 = g_rowptr[node], s1 = g_rowptr[node + 1];

    float den = 0.f, T1 = 0.f, T2 = 0.f;
    int j = s0;
    for (; j + 4 <= s1; j += 4) {
        int2 e0 = g_col[j];
        int2 e1 = g_col[j + 1];
        int2 e2 = g_col[j + 2];
        int2 e3 = g_col[j + 3];
        float w0 = g_wT[(size_t)e0.y * NG + g];
        float x0 = g_xT[(size_t)e0.x * NG + g];
        float w1 = g_wT[(size_t)e1.y * NG + g];
        float x1 = g_xT[(size_t)e1.x * NG + g];
        float w2 = g_wT[(size_t)e2.y * NG + g];
        float x2 = g_xT[(size_t)e2.x * NG + g];
        float w3 = g_wT[(size_t)e3.y * NG + g];
        float x3 = g_xT[(size_t)e3.x * NG + g];

        float v0 = fmaf(cL, x0, fmaf(cE, w0, based));
        float v1 = fmaf(cL, x1, fmaf(cE, w1, based));
        float v2 = fmaf(cL, x2, fmaf(cE, w2, based));
        float v3 = fmaf(cL, x3, fmaf(cE, w3, based));
        v0 = (v0 > 0.f) ? v0 : NEG_SLOPE * v0;
        v1 = (v1 > 0.f) ? v1 : NEG_SLOPE * v1;
        v2 = (v2 > 0.f) ? v2 : NEG_SLOPE * v2;
        v3 = (v3 > 0.f) ? v3 : NEG_SLOPE * v3;
        float p0 = __expf(v0);
        float p1 = __expf(v1);
        float p2 = __expf(v2);
        float p3 = __expf(v3);
        den += p0; T1 = fmaf(p0, x0, T1); T2 = fmaf(p0, w0, T2);
        den += p1; T1 = fmaf(p1, x1, T1); T2 = fmaf(p1, w1, T2);
        den += p2; T1 = fmaf(p2, x2, T1); T2 = fmaf(p2, w2, T2);
        den += p3; T1 = fmaf(p3, x3, T1); T2 = fmaf(p3, w3, T2);
    }
    for (; j < s1; j++) {
        int2 se = g_col[j];
        float w  = g_wT[(size_t)se.y * NG + g];
        float xs = g_xT[(size_t)se.x * NG + g];
        float v = fmaf(cL, xs, fmaf(cE, w, based));
        v = (v > 0.f) ? v : NEG_SLOPE * v;
        float p = __expf(v);
        den += p; T1 = fmaf(p, xs, T1); T2 = fmaf(p, w, T2);
    }
    if (s1 > s0) {
        float inv = 1.0f / den;
        atomicAdd(&g_S[g].x, T1 * inv);
        atomicAdd(&g_S[g].y, T2 * inv);
    }
}

// =====================================================================
// K5: fused LSTM + fc + fcc. One CTA per batch element; hs stays in smem.
// =====================================================================
__device__ __forceinline__ float sigm(float x) { return 1.0f / (1.0f + __expf(-x)); }

__global__ void lstm_head_kernel(const float* __restrict__ W_node,
                                 const float* __restrict__ W_edge,
                                 const float* __restrict__ gat_b,
                                 const float* __restrict__ w_ih,
                                 const float* __restrict__ w_hh,
                                 const float* __restrict__ b_ih,
                                 const float* __restrict__ b_hh,
                                 const float* __restrict__ fc_w,
                                 const float* __restrict__ fc_b,
                                 const float* __restrict__ fcc_w,
                                 const float* __restrict__ fcc_b,
                                 float* __restrict__ out) {
    int b = blockIdx.x;          // 0..15
    int tid = threadIdx.x;       // 128 threads
    __shared__ float h[HID], c[HID], gates[4 * HID], xt[OUTF];
    __shared__ float hs[TT][HID];
    __shared__ float fcv[TT * 160];

    float wih[OUTF];
    float whh[HID];
    float bsum = 0.f;
    if (tid < 4 * HID) {
        #pragma unroll
        for (int k = 0; k < OUTF; k++) wih[k] = w_ih[tid * OUTF + k];
        #pragma unroll
        for (int j = 0; j < HID; j++) whh[j] = w_hh[tid * HID + j];
        bsum = b_ih[tid] + b_hh[tid];
    }
    if (tid < HID) { h[tid] = 0.f; c[tid] = 0.f; }
    __syncthreads();

    for (int t = 0; t < TT; t++) {
        if (tid < OUTF) {
            float2 S = g_S[b * TT + t];
            xt[tid] = fmaf(S.x, W_node[tid], S.y * W_edge[tid]) * (1.0f / N_NODES)
                      + gat_b[tid];
        }
        __syncthreads();
        if (tid < 4 * HID) {
            float acc = bsum;
            #pragma unroll
            for (int k = 0; k < OUTF; k++) acc = fmaf(wih[k], xt[k], acc);
            #pragma unroll
            for (int j = 0; j < HID; j++) acc = fmaf(whh[j], h[j], acc);
            gates[tid] = acc;
        }
        __syncthreads();
        if (tid < HID) {
            float gi = sigm(gates[tid]);
            float gf = sigm(gates[HID + tid]);
            float gc = tanhf(gates[2 * HID + tid]);
            float go = sigm(gates[3 * HID + tid]);
            float cn = fmaf(gf, c[tid], gi * gc);
            c[tid] = cn;
            float hn = go * tanhf(cn);
            h[tid] = hn;
            hs[t][tid] = hn;
        }
        __syncthreads();
    }

    for (int idx = tid; idx < TT * 160; idx += 128) {
        int r = idx / 160, m = idx % 160;
        float acc = fc_b[m];
        #pragma unroll
        for (int k = 0; k < HID; k++) acc = fmaf(hs[r][k], fc_w[m * HID + k], acc);
        fcv[idx] = acc;
    }
    __syncthreads();

    for (int idx = tid; idx < TT * 20; idx += 128) {
        int r = idx / 20, m = idx % 20;
        const float* fv = &fcv[r * 160];
        float acc = fcc_b[m];
        #pragma unroll 8
        for (int q = 0; q < 160; q++) acc = fmaf(fv[q], fcc_w[m * 160 + q], acc);
        out[(b * TT + r) * 20 + m] = acc;
    }
}

// ---------------- launch ----------------
extern "C" void kernel_launch(void* const* d_in, const int* in_sizes, int n_in,
                              void* d_out, int out_size) {
    const float* x      = (const float*)d_in[0];
    const float* ew     = (const float*)d_in[1];
    const int*   src    = (const int*)  d_in[2];
    const int*   dst    = (const int*)  d_in[3];
    const float* W_node = (const float*)d_in[4];
    const float* W_edge = (const float*)d_in[5];
    const float* attn_l = (const float*)d_in[6];
    const float* attn_e = (const float*)d_in[7];
    const float* attn_r = (const float*)d_in[8];
    const float* gat_b  = (const float*)d_in[9];
    const float* w_ih   = (const float*)d_in[10];
    const float* w_hh   = (const float*)d_in[11];
    const float* b_ih   = (const float*)d_in[12];
    const float* b_hh   = (const float*)d_in[13];
    const float* fc_w   = (const float*)d_in[14];
    const float* fc_b   = (const float*)d_in[15];
    const float* fcc_w  = (const float*)d_in[16];
    const float* fcc_b  = (const float*)d_in[17];
    float* out = (float*)d_out;

    prep_kernel<<<10755, 256>>>(x, ew, dst);
    scan_kernel<<<1, 1024>>>();
    scatter_kernel<<<(N_EDGES + 255) / 256, 256>>>(src, dst);
    gat_kernel<<<N_NODES, NG>>>(W_node, W_edge, attn_l, attn_e, attn_r);
    lstm_head_kernel<<<BB, 128>>>(W_node, W_edge, gat_b, w_ih, w_hh, b_ih, b_hh,
                                  fc_w, fc_b, fcc_w, fcc_b, out);
}

// round 5
// speedup vs baseline: 1.5658x; 1.1617x over previous
#include <cuda_runtime.h>

#define N_NODES 2000
#define N_EDGES 32000
#define NG      320      // B*T graphs
#define OUTF    8
#define HID     24
#define BB      16
#define TT      20
#define STRIP   4
#define NEG_SLOPE 0.2f

// ---------------- scratch (device globals; no allocs allowed) ----------------
__device__ float  g_wT[(size_t)N_EDGES * NG];   // [csr_pos][320]  CSR-ordered!
__device__ float  g_xT[(size_t)N_NODES * NG];   // [node][320]
__device__ int    g_pos[N_EDGES];               // orig edge -> CSR slot
__device__ int    g_srcc[N_EDGES];              // CSR slot -> src node
__device__ int    g_rowptr[N_NODES + 1];
__device__ int    g_deg[N_NODES];               // re-zeroed by scan for next replay
__device__ int    g_cur[N_NODES];               // re-zeroed by gat for next replay
__device__ float2 g_S[NG];                      // per-graph (S1, S2); zeroed by scan

// =====================================================================
// K1: x-transpose [320][N] -> [N][320]  +  degree histogram
//   blocks [0,630): transpose tiles (63 x-tiles x 10 g-tiles)
//   blocks [630,755): histogram (125 blocks x 256 = 32000)
// =====================================================================
__global__ void xtrans_hist_kernel(const float* __restrict__ xin,
                                   const int* __restrict__ dst) {
    __shared__ float tile[32][33];
    int bid = blockIdx.x;
    if (bid < 630) {
        int tx = threadIdx.x & 31, ty = threadIdx.x >> 5;
        int cb = (bid % 63) * 32;            // node base
        int rb = (bid / 63) * 32;            // graph base
        #pragma unroll
        for (int i = 0; i < 32; i += 8) {
            int c = cb + tx;
            tile[ty + i][tx] = (c < N_NODES)
                ? xin[(size_t)(rb + ty + i) * N_NODES + c] : 0.0f;
        }
        __syncthreads();
        #pragma unroll
        for (int i = 0; i < 32; i += 8) {
            int c = cb + ty + i;
            if (c < N_NODES) g_xT[(size_t)c * NG + rb + tx] = tile[tx][ty + i];
        }
    } else {
        int e = (bid - 630) * 256 + threadIdx.x;
        if (e < N_EDGES) atomicAdd(&g_deg[dst[e]], 1);
    }
}

// =====================================================================
// K2: scan (deg -> rowptr); recycles g_deg (next replay) and zeroes g_S
// =====================================================================
__global__ void scan_kernel() {
    __shared__ int sh[1024];
    int t = threadIdx.x;
    int a = (2 * t     < N_NODES) ? g_deg[2 * t]     : 0;
    int b = (2 * t + 1 < N_NODES) ? g_deg[2 * t + 1] : 0;
    int v = a + b;
    sh[t] = v;
    __syncthreads();
    for (int off = 1; off < 1024; off <<= 1) {
        int add = (t >= off) ? sh[t - off] : 0;
        __syncthreads();
        sh[t] += add;
        __syncthreads();
    }
    int incl = sh[t];
    int excl = incl - v;
    if (2 * t     < N_NODES) { g_rowptr[2 * t]     = excl;     g_deg[2 * t]     = 0; }
    if (2 * t + 1 < N_NODES) { g_rowptr[2 * t + 1] = excl + a; g_deg[2 * t + 1] = 0; }
    if (t == 1023) g_rowptr[N_NODES] = incl;
    if (t < NG) g_S[t] = make_float2(0.0f, 0.0f);
}

// =====================================================================
// K3: scatter — build edge->CSR permutation and CSR src list
// =====================================================================
__global__ void scatter_kernel(const int* __restrict__ src, const int* __restrict__ dst) {
    int e = blockIdx.x * blockDim.x + threadIdx.x;
    if (e < N_EDGES) {
        int d = dst[e];
        int pos = g_rowptr[d] + atomicAdd(&g_cur[d], 1);
        g_pos[e] = pos;
        g_srcc[pos] = src[e];
    }
}

// =====================================================================
// K4: w-transpose [320][E] -> CSR-permuted [E][320]
//   1000 edge-tiles x 10 graph-tiles = 10000 blocks
// =====================================================================
__global__ void wtrans_kernel(const float* __restrict__ win) {
    __shared__ float tile[32][33];
    __shared__ int rowmap[32];
    int tx = threadIdx.x & 31, ty = threadIdx.x >> 5;
    int cb = (blockIdx.x % 1000) * 32;       // edge base
    int rb = (blockIdx.x / 1000) * 32;       // graph base
    if (threadIdx.x < 32) rowmap[threadIdx.x] = g_pos[cb + threadIdx.x];
    #pragma unroll
    for (int i = 0; i < 32; i += 8)
        tile[ty + i][tx] = win[(size_t)(rb + ty + i) * N_EDGES + cb + tx];
    __syncthreads();
    #pragma unroll
    for (int i = 0; i < 32; i += 8)
        g_wT[(size_t)rowmap[ty + i] * NG + rb + tx] = tile[tx][ty + i];
}

// =====================================================================
// K5: GAT reduction. CTA = strip of 4 nodes (500 CTAs, 320 thr), thread=graph.
//   w rows are read in STREAMING CSR order; only g_xT (2.5MB, L2-hot) is a
//   gather. Per-thread accumulation over the strip -> 1 atomic pair/thread.
//   Single pass per edge (logits O(0.1) -> exp safe without max-shift).
// =====================================================================
__global__ void __launch_bounds__(NG) gat_kernel(const float* __restrict__ W_node,
                           const float* __restrict__ W_edge,
                           const float* __restrict__ attn_l,
                           const float* __restrict__ attn_e,
                           const float* __restrict__ attn_r) {
    int g = threadIdx.x;                     // graph 0..319
    int gid = blockIdx.x * NG + g;
    if (gid < N_NODES) g_cur[gid] = 0;       // recycle for next replay

    float cL = 0.f, cE = 0.f, cR = 0.f;
    #pragma unroll
    for (int o = 0; o < OUTF; o++) {
        float wn = __ldg(&W_node[o]);
        float we = __ldg(&W_edge[o]);
        cL = fmaf(wn, __ldg(&attn_l[o]), cL);
        cR = fmaf(wn, __ldg(&attn_r[o]), cR);
        cE = fmaf(we, __ldg(&attn_e[o]), cE);
    }

    int n0 = blockIdx.x * STRIP;
    float acc1 = 0.f, acc2 = 0.f;

    #pragma unroll
    for (int nn = 0; nn < STRIP; nn++) {
        int node = n0 + nn;
        float xd = g_xT[(size_t)node * NG + g];
        float based = cR * xd;
        int s0 = g_rowptr[node], s1 = g_rowptr[node + 1];

        float den = 0.f, T1 = 0.f, T2 = 0.f;
        int j = s0;
        for (; j + 4 <= s1; j += 4) {
            int sa = g_srcc[j];
            int sb = g_srcc[j + 1];
            int sc = g_srcc[j + 2];
            int sd = g_srcc[j + 3];
            float w0 = g_wT[(size_t)(j    ) * NG + g];
            float w1 = g_wT[(size_t)(j + 1) * NG + g];
            float w2 = g_wT[(size_t)(j + 2) * NG + g];
            float w3 = g_wT[(size_t)(j + 3) * NG + g];
            float x0 = g_xT[(size_t)sa * NG + g];
            float x1 = g_xT[(size_t)sb * NG + g];
            float x2 = g_xT[(size_t)sc * NG + g];
            float x3 = g_xT[(size_t)sd * NG + g];

            float v0 = fmaf(cL, x0, fmaf(cE, w0, based));
            float v1 = fmaf(cL, x1, fmaf(cE, w1, based));
            float v2 = fmaf(cL, x2, fmaf(cE, w2, based));
            float v3 = fmaf(cL, x3, fmaf(cE, w3, based));
            v0 = fmaxf(v0, NEG_SLOPE * v0);
            v1 = fmaxf(v1, NEG_SLOPE * v1);
            v2 = fmaxf(v2, NEG_SLOPE * v2);
            v3 = fmaxf(v3, NEG_SLOPE * v3);
            float p0 = __expf(v0);
            float p1 = __expf(v1);
            float p2 = __expf(v2);
            float p3 = __expf(v3);
            den += p0; T1 = fmaf(p0, x0, T1); T2 = fmaf(p0, w0, T2);
            den += p1; T1 = fmaf(p1, x1, T1); T2 = fmaf(p1, w1, T2);
            den += p2; T1 = fmaf(p2, x2, T1); T2 = fmaf(p2, w2, T2);
            den += p3; T1 = fmaf(p3, x3, T1); T2 = fmaf(p3, w3, T2);
        }
        for (; j < s1; j++) {
            float w  = g_wT[(size_t)j * NG + g];
            float xs = g_xT[(size_t)g_srcc[j] * NG + g];
            float v = fmaf(cL, xs, fmaf(cE, w, based));
            v = fmaxf(v, NEG_SLOPE * v);
            float p = __expf(v);
            den += p; T1 = fmaf(p, xs, T1); T2 = fmaf(p, w, T2);
        }
        if (s1 > s0) {
            float inv = 1.0f / den;
            acc1 = fmaf(T1, inv, acc1);
            acc2 = fmaf(T2, inv, acc2);
        }
    }
    atomicAdd(&g_S[g].x, acc1);
    atomicAdd(&g_S[g].y, acc2);
}

// =====================================================================
// K6: fused LSTM + fc + fcc. One CTA per batch element; hs stays in smem.
// =====================================================================
__device__ __forceinline__ float sigm(float x) { return 1.0f / (1.0f + __expf(-x)); }

__global__ void lstm_head_kernel(const float* __restrict__ W_node,
                                 const float* __restrict__ W_edge,
                                 const float* __restrict__ gat_b,
                                 const float* __restrict__ w_ih,
                                 const float* __restrict__ w_hh,
                                 const float* __restrict__ b_ih,
                                 const float* __restrict__ b_hh,
                                 const float* __restrict__ fc_w,
                                 const float* __restrict__ fc_b,
                                 const float* __restrict__ fcc_w,
                                 const float* __restrict__ fcc_b,
                                 float* __restrict__ out) {
    int b = blockIdx.x;          // 0..15
    int tid = threadIdx.x;       // 128 threads
    __shared__ float h[HID], c[HID], gates[4 * HID], xt[OUTF];
    __shared__ float hs[TT][HID];
    __shared__ float fcv[TT * 160];

    float wih[OUTF];
    float whh[HID];
    float bsum = 0.f;
    if (tid < 4 * HID) {
        #pragma unroll
        for (int k = 0; k < OUTF; k++) wih[k] = w_ih[tid * OUTF + k];
        #pragma unroll
        for (int j = 0; j < HID; j++) whh[j] = w_hh[tid * HID + j];
        bsum = b_ih[tid] + b_hh[tid];
    }
    if (tid < HID) { h[tid] = 0.f; c[tid] = 0.f; }
    __syncthreads();

    for (int t = 0; t < TT; t++) {
        if (tid < OUTF) {
            float2 S = g_S[b * TT + t];
            xt[tid] = fmaf(S.x, W_node[tid], S.y * W_edge[tid]) * (1.0f / N_NODES)
                      + gat_b[tid];
        }
        __syncthreads();
        if (tid < 4 * HID) {
            float acc = bsum;
            #pragma unroll
            for (int k = 0; k < OUTF; k++) acc = fmaf(wih[k], xt[k], acc);
            #pragma unroll
            for (int j = 0; j < HID; j++) acc = fmaf(whh[j], h[j], acc);
            gates[tid] = acc;
        }
        __syncthreads();
        if (tid < HID) {
            float gi = sigm(gates[tid]);
            float gf = sigm(gates[HID + tid]);
            float gc = tanhf(gates[2 * HID + tid]);
            float go = sigm(gates[3 * HID + tid]);
            float cn = fmaf(gf, c[tid], gi * gc);
            c[tid] = cn;
            float hn = go * tanhf(cn);
            h[tid] = hn;
            hs[t][tid] = hn;
        }
        __syncthreads();
    }

    for (int idx = tid; idx < TT * 160; idx += 128) {
        int r = idx / 160, m = idx % 160;
        float acc = fc_b[m];
        #pragma unroll
        for (int k = 0; k < HID; k++) acc = fmaf(hs[r][k], fc_w[m * HID + k], acc);
        fcv[idx] = acc;
    }
    __syncthreads();

    for (int idx = tid; idx < TT * 20; idx += 128) {
        int r = idx / 20, m = idx % 20;
        const float* fv = &fcv[r * 160];
        float acc = fcc_b[m];
        #pragma unroll 8
        for (int q = 0; q < 160; q++) acc = fmaf(fv[q], fcc_w[m * 160 + q], acc);
        out[(b * TT + r) * 20 + m] = acc;
    }
}

// ---------------- launch ----------------
extern "C" void kernel_launch(void* const* d_in, const int* in_sizes, int n_in,
                              void* d_out, int out_size) {
    const float* x      = (const float*)d_in[0];
    const float* ew     = (const float*)d_in[1];
    const int*   src    = (const int*)  d_in[2];
    const int*   dst    = (const int*)  d_in[3];
    const float* W_node = (const float*)d_in[4];
    const float* W_edge = (const float*)d_in[5];
    const float* attn_l = (const float*)d_in[6];
    const float* attn_e = (const float*)d_in[7];
    const float* attn_r = (const float*)d_in[8];
    const float* gat_b  = (const float*)d_in[9];
    const float* w_ih   = (const float*)d_in[10];
    const float* w_hh   = (const float*)d_in[11];
    const float* b_ih   = (const float*)d_in[12];
    const float* b_hh   = (const float*)d_in[13];
    const float* fc_w   = (const float*)d_in[14];
    const float* fc_b   = (const float*)d_in[15];
    const float* fcc_w  = (const float*)d_in[16];
    const float* fcc_b  = (const float*)d_in[17];
    float* out = (float*)d_out;

    xtrans_hist_kernel<<<755, 256>>>(x, dst);
    scan_kernel<<<1, 1024>>>();
    scatter_kernel<<<125, 256>>>(src, dst);
    wtrans_kernel<<<10000, 256>>>(ew);
    gat_kernel<<<N_NODES / STRIP, NG>>>(W_node, W_edge, attn_l, attn_e, attn_r);
    lstm_head_kernel<<<BB, 128>>>(W_node, W_edge, gat_b, w_ih, w_hh, b_ih, b_hh,
                                  fc_w, fc_b, fcc_w, fcc_b, out);
}

// round 6
// speedup vs baseline: 1.5964x; 1.0195x over previous
#include <cuda_runtime.h>

#define N_NODES 2000
#define N_EDGES 32000
#define NG      320      // B*T graphs
#define OUTF    8
#define HID     24
#define BB      16
#define TT      20
#define STRIP   4
#define NEG_SLOPE 0.2f

// ---------------- scratch (device globals; no allocs allowed) ----------------
__device__ float  g_wT[(size_t)N_EDGES * NG];   // [csr_pos][320]  CSR-ordered
__device__ float  g_xT[(size_t)N_NODES * NG];   // [node][320]
__device__ int    g_srcc[N_EDGES];              // CSR slot -> src node
__device__ int    g_rowptr[N_NODES + 1];
__device__ int    g_deg[N_NODES];               // zeroed by K1 scan-block each call
__device__ int    g_cur[N_NODES];               // zeroed by K1 scan-block each call
__device__ float2 g_S[NG];                      // zeroed by K1 scan-block each call
__device__ unsigned int g_cnt1 = 0;             // K1 fan-in counter (reset by last block)

// =====================================================================
// K1: x-transpose [320][N] -> [N][320]  +  degree histogram;
//     LAST block (fan-in) does: scan deg->rowptr, zero deg/cur/S, reset cnt.
//   blocks [0,630): transpose tiles (63 node-tiles x 10 graph-tiles)
//   blocks [630,755): histogram (125 blocks x 256 = 32000 edges)
// =====================================================================
__global__ void xtrans_hist_scan_kernel(const float* __restrict__ xin,
                                        const int* __restrict__ dst) {
    __shared__ float tile[32][33];
    __shared__ int ssum[256];
    __shared__ int sflag;
    int bid = blockIdx.x;
    int tid = threadIdx.x;

    if (bid < 630) {
        int tx = tid & 31, ty = tid >> 5;
        int cb = (bid % 63) * 32;            // node base
        int rb = (bid / 63) * 32;            // graph base
        #pragma unroll
        for (int i = 0; i < 32; i += 8) {
            int c = cb + tx;
            tile[ty + i][tx] = (c < N_NODES)
                ? xin[(size_t)(rb + ty + i) * N_NODES + c] : 0.0f;
        }
        __syncthreads();
        #pragma unroll
        for (int i = 0; i < 32; i += 8) {
            int c = cb + ty + i;
            if (c < N_NODES) g_xT[(size_t)c * NG + rb + tx] = tile[tx][ty + i];
        }
    } else {
        int e = (bid - 630) * 256 + tid;
        if (e < N_EDGES) atomicAdd(&g_deg[dst[e]], 1);
    }

    // ---- fan-in: last block to finish performs the scan ----
    __threadfence();
    __syncthreads();
    if (tid == 0)
        sflag = (atomicAdd(&g_cnt1, 1) == gridDim.x - 1) ? 1 : 0;
    __syncthreads();
    if (!sflag) return;
    __threadfence();

    // scan: 256 threads, 8 bins each (250 active)
    int base = tid * 8;
    int v[8];
    int run = 0;
    if (tid < 250) {
        #pragma unroll
        for (int k = 0; k < 8; k++) {
            int d = g_deg[base + k];
            v[k] = run;                      // exclusive within thread
            run += d;
        }
    } else {
        #pragma unroll
        for (int k = 0; k < 8; k++) v[k] = 0;
    }
    ssum[tid] = run;
    __syncthreads();
    for (int off = 1; off < 256; off <<= 1) {
        int a = (tid >= off) ? ssum[tid - off] : 0;
        __syncthreads();
        ssum[tid] += a;
        __syncthreads();
    }
    int excl = ssum[tid] - run;
    if (tid < 250) {
        #pragma unroll
        for (int k = 0; k < 8; k++) {
            g_rowptr[base + k] = excl + v[k];
            g_deg[base + k] = 0;             // recycle for next replay
            g_cur[base + k] = 0;             // ready for K2 scatter
        }
    }
    if (tid == 249) g_rowptr[N_NODES] = excl + run;
    for (int i = tid; i < NG; i += 256) g_S[i] = make_float2(0.0f, 0.0f);
    if (tid == 0) g_cnt1 = 0;                // reset fan-in counter
}

// =====================================================================
// K2: fused scatter + CSR-permuted w-transpose.
//   1000 blocks x 320 threads; block owns original edges [eb, eb+32).
//   Threads 0..31 scatter those edges (pos is block-local!), then the
//   block transposes its 32e x 320g tile of win and writes each edge's
//   320-float row to g_wT[pos]. float4 loads; smem stride 33 (conflict-free).
// =====================================================================
__global__ void __launch_bounds__(NG) scat_wtrans_kernel(
        const float* __restrict__ win,
        const int* __restrict__ src,
        const int* __restrict__ dst) {
    __shared__ float tile[NG][33];           // [g][e], 42.2 KB
    __shared__ int s_pos[32];
    int tid = threadIdx.x;
    int eb = blockIdx.x * 32;

    if (tid < 32) {
        int e = eb + tid;
        int d = dst[e];
        int p = g_rowptr[d] + atomicAdd(&g_cur[d], 1);
        s_pos[tid] = p;
        g_srcc[p] = src[e];
    }

    // load 320 rows x 32 edges, float4 (8 float4 per row); 8 iters/thread
    #pragma unroll
    for (int r = 0; r < 8; r++) {
        int idx = r * NG + tid;              // 0..2559
        int g = idx >> 3, q = idx & 7;
        float4 vv = *(const float4*)&win[(size_t)g * N_EDGES + eb + q * 4];
        tile[g][q * 4 + 0] = vv.x;
        tile[g][q * 4 + 1] = vv.y;
        tile[g][q * 4 + 2] = vv.z;
        tile[g][q * 4 + 3] = vv.w;
    }
    __syncthreads();

    // write: per edge, 320 contiguous floats to the permuted row
    #pragma unroll 8
    for (int e = 0; e < 32; e++) {
        g_wT[(size_t)s_pos[e] * NG + tid] = tile[tid][e];
    }
}

// =====================================================================
// K3: GAT reduction. CTA = strip of 4 nodes (500 CTAs, 320 thr), thread=graph.
//   w rows streamed in CSR order; g_xT (2.5MB, L2-hot) is the only gather.
//   Single pass (logits O(0.1) -> exp safe without max-shift).
// =====================================================================
__global__ void __launch_bounds__(NG) gat_kernel(const float* __restrict__ W_node,
                           const float* __restrict__ W_edge,
                           const float* __restrict__ attn_l,
                           const float* __restrict__ attn_e,
                           const float* __restrict__ attn_r) {
    int g = threadIdx.x;                     // graph 0..319

    float cL = 0.f, cE = 0.f, cR = 0.f;
    #pragma unroll
    for (int o = 0; o < OUTF; o++) {
        float wn = __ldg(&W_node[o]);
        float we = __ldg(&W_edge[o]);
        cL = fmaf(wn, __ldg(&attn_l[o]), cL);
        cR = fmaf(wn, __ldg(&attn_r[o]), cR);
        cE = fmaf(we, __ldg(&attn_e[o]), cE);
    }

    int n0 = blockIdx.x * STRIP;
    float acc1 = 0.f, acc2 = 0.f;

    #pragma unroll
    for (int nn = 0; nn < STRIP; nn++) {
        int node = n0 + nn;
        float xd = g_xT[(size_t)node * NG + g];
        float based = cR * xd;
        int s0 = g_rowptr[node], s1 = g_rowptr[node + 1];

        float den = 0.f, T1 = 0.f, T2 = 0.f;
        int j = s0;
        for (; j + 4 <= s1; j += 4) {
            int sa = g_srcc[j];
            int sb = g_srcc[j + 1];
            int sc = g_srcc[j + 2];
            int sd = g_srcc[j + 3];
            float w0 = g_wT[(size_t)(j    ) * NG + g];
            float w1 = g_wT[(size_t)(j + 1) * NG + g];
            float w2 = g_wT[(size_t)(j + 2) * NG + g];
            float w3 = g_wT[(size_t)(j + 3) * NG + g];
            float x0 = g_xT[(size_t)sa * NG + g];
            float x1 = g_xT[(size_t)sb * NG + g];
            float x2 = g_xT[(size_t)sc * NG + g];
            float x3 = g_xT[(size_t)sd * NG + g];

            float v0 = fmaf(cL, x0, fmaf(cE, w0, based));
            float v1 = fmaf(cL, x1, fmaf(cE, w1, based));
            float v2 = fmaf(cL, x2, fmaf(cE, w2, based));
            float v3 = fmaf(cL, x3, fmaf(cE, w3, based));
            v0 = fmaxf(v0, NEG_SLOPE * v0);
            v1 = fmaxf(v1, NEG_SLOPE * v1);
            v2 = fmaxf(v2, NEG_SLOPE * v2);
            v3 = fmaxf(v3, NEG_SLOPE * v3);
            float p0 = __expf(v0);
            float p1 = __expf(v1);
            float p2 = __expf(v2);
            float p3 = __expf(v3);
            den += p0; T1 = fmaf(p0, x0, T1); T2 = fmaf(p0, w0, T2);
            den += p1; T1 = fmaf(p1, x1, T1); T2 = fmaf(p1, w1, T2);
            den += p2; T1 = fmaf(p2, x2, T1); T2 = fmaf(p2, w2, T2);
            den += p3; T1 = fmaf(p3, x3, T1); T2 = fmaf(p3, w3, T2);
        }
        for (; j < s1; j++) {
            float w  = g_wT[(size_t)j * NG + g];
            float xs = g_xT[(size_t)g_srcc[j] * NG + g];
            float v = fmaf(cL, xs, fmaf(cE, w, based));
            v = fmaxf(v, NEG_SLOPE * v);
            float p = __expf(v);
            den += p; T1 = fmaf(p, xs, T1); T2 = fmaf(p, w, T2);
        }
        if (s1 > s0) {
            float inv = 1.0f / den;
            acc1 = fmaf(T1, inv, acc1);
            acc2 = fmaf(T2, inv, acc2);
        }
    }
    atomicAdd(&g_S[g].x, acc1);
    atomicAdd(&g_S[g].y, acc2);
}

// =====================================================================
// K4: fused LSTM + fc + fcc. One CTA per batch element; hs stays in smem.
// =====================================================================
__device__ __forceinline__ float sigm(float x) { return 1.0f / (1.0f + __expf(-x)); }

__global__ void lstm_head_kernel(const float* __restrict__ W_node,
                                 const float* __restrict__ W_edge,
                                 const float* __restrict__ gat_b,
                                 const float* __restrict__ w_ih,
                                 const float* __restrict__ w_hh,
                                 const float* __restrict__ b_ih,
                                 const float* __restrict__ b_hh,
                                 const float* __restrict__ fc_w,
                                 const float* __restrict__ fc_b,
                                 const float* __restrict__ fcc_w,
                                 const float* __restrict__ fcc_b,
                                 float* __restrict__ out) {
    int b = blockIdx.x;          // 0..15
    int tid = threadIdx.x;       // 128 threads
    __shared__ float h[HID], c[HID], gates[4 * HID], xt[OUTF];
    __shared__ float hs[TT][HID];
    __shared__ float fcv[TT * 160];

    float wih[OUTF];
    float whh[HID];
    float bsum = 0.f;
    if (tid < 4 * HID) {
        #pragma unroll
        for (int k = 0; k < OUTF; k++) wih[k] = w_ih[tid * OUTF + k];
        #pragma unroll
        for (int j = 0; j < HID; j++) whh[j] = w_hh[tid * HID + j];
        bsum = b_ih[tid] + b_hh[tid];
    }
    if (tid < HID) { h[tid] = 0.f; c[tid] = 0.f; }
    __syncthreads();

    for (int t = 0; t < TT; t++) {
        if (tid < OUTF) {
            float2 S = g_S[b * TT + t];
            xt[tid] = fmaf(S.x, W_node[tid], S.y * W_edge[tid]) * (1.0f / N_NODES)
                      + gat_b[tid];
        }
        __syncthreads();
        if (tid < 4 * HID) {
            float acc = bsum;
            #pragma unroll
            for (int k = 0; k < OUTF; k++) acc = fmaf(wih[k], xt[k], acc);
            #pragma unroll
            for (int j = 0; j < HID; j++) acc = fmaf(whh[j], h[j], acc);
            gates[tid] = acc;
        }
        __syncthreads();
        if (tid < HID) {
            float gi = sigm(gates[tid]);
            float gf = sigm(gates[HID + tid]);
            float gc = tanhf(gates[2 * HID + tid]);
            float go = sigm(gates[3 * HID + tid]);
            float cn = fmaf(gf, c[tid], gi * gc);
            c[tid] = cn;
            float hn = go * tanhf(cn);
            h[tid] = hn;
            hs[t][tid] = hn;
        }
        __syncthreads();
    }

    for (int idx = tid; idx < TT * 160; idx += 128) {
        int r = idx / 160, m = idx % 160;
        float acc = fc_b[m];
        #pragma unroll
        for (int k = 0; k < HID; k++) acc = fmaf(hs[r][k], fc_w[m * HID + k], acc);
        fcv[idx] = acc;
    }
    __syncthreads();

    for (int idx = tid; idx < TT * 20; idx += 128) {
        int r = idx / 20, m = idx % 20;
        const float* fv = &fcv[r * 160];
        float acc = fcc_b[m];
        #pragma unroll 8
        for (int q = 0; q < 160; q++) acc = fmaf(fv[q], fcc_w[m * 160 + q], acc);
        out[(b * TT + r) * 20 + m] = acc;
    }
}

// ---------------- launch ----------------
extern "C" void kernel_launch(void* const* d_in, const int* in_sizes, int n_in,
                              void* d_out, int out_size) {
    const float* x      = (const float*)d_in[0];
    const float* ew     = (const float*)d_in[1];
    const int*   src    = (const int*)  d_in[2];
    const int*   dst    = (const int*)  d_in[3];
    const float* W_node = (const float*)d_in[4];
    const float* W_edge = (const float*)d_in[5];
    const float* attn_l = (const float*)d_in[6];
    const float* attn_e = (const float*)d_in[7];
    const float* attn_r = (const float*)d_in[8];
    const float* gat_b  = (const float*)d_in[9];
    const float* w_ih   = (const float*)d_in[10];
    const float* w_hh   = (const float*)d_in[11];
    const float* b_ih   = (const float*)d_in[12];
    const float* b_hh   = (const float*)d_in[13];
    const float* fc_w   = (const float*)d_in[14];
    const float* fc_b   = (const float*)d_in[15];
    const float* fcc_w  = (const float*)d_in[16];
    const float* fcc_b  = (const float*)d_in[17];
    float* out = (float*)d_out;

    xtrans_hist_scan_kernel<<<755, 256>>>(x, dst);
    scat_wtrans_kernel<<<N_EDGES / 32, NG>>>(ew, src, dst);
    gat_kernel<<<N_NODES / STRIP, NG>>>(W_node, W_edge, attn_l, attn_e, attn_r);
    lstm_head_kernel<<<BB, 128>>>(W_node, W_edge, gat_b, w_ih, w_hh, b_ih, b_hh,
                                  fc_w, fc_b, fcc_w, fcc_b, out);
}

// round 7
// speedup vs baseline: 2.7558x; 1.7263x over previous
#include <cuda_runtime.h>

#define N_NODES 2000
#define N_EDGES 32000
#define NG      320      // B*T graphs
#define OUTF    8
#define HID     24
#define BB      16
#define TT      20
#define STRIP   4
#define NEG_SLOPE 0.2f

// ---------------- scratch (device globals; no allocs allowed) ----------------
__device__ float  g_wT[(size_t)N_EDGES * NG];   // [csr_pos][320]  CSR-ordered
__device__ float  g_xT[(size_t)N_NODES * NG];   // [node][320]
__device__ int    g_srcc[N_EDGES];              // CSR slot -> src node
__device__ int    g_rowptr[N_NODES + 1];
__device__ int    g_deg[N_NODES];               // zeroed by K1 scan-block each call
__device__ int    g_cur[N_NODES];               // zeroed by K1 scan-block each call
__device__ float2 g_S[NG];                      // zeroed by K1 scan-block each call
__device__ unsigned int g_cnt1 = 0;             // K1 fan-in counter (reset by last block)
__device__ float  g_M[20 * HID];                // composed head: fcc_w @ fc_w  [20][24]
__device__ float  g_bias2[20];                  // fcc_w @ fc_b + fcc_b

// =====================================================================
// K1: x-transpose [320][N] -> [N][320]  +  degree histogram;
//     LAST block (fan-in) does: scan deg->rowptr, zero deg/cur/S, reset cnt.
// =====================================================================
__global__ void xtrans_hist_scan_kernel(const float* __restrict__ xin,
                                        const int* __restrict__ dst) {
    __shared__ float tile[32][33];
    __shared__ int ssum[256];
    __shared__ int sflag;
    int bid = blockIdx.x;
    int tid = threadIdx.x;

    if (bid < 630) {
        int tx = tid & 31, ty = tid >> 5;
        int cb = (bid % 63) * 32;            // node base
        int rb = (bid / 63) * 32;            // graph base
        #pragma unroll
        for (int i = 0; i < 32; i += 8) {
            int c = cb + tx;
            tile[ty + i][tx] = (c < N_NODES)
                ? xin[(size_t)(rb + ty + i) * N_NODES + c] : 0.0f;
        }
        __syncthreads();
        #pragma unroll
        for (int i = 0; i < 32; i += 8) {
            int c = cb + ty + i;
            if (c < N_NODES) g_xT[(size_t)c * NG + rb + tx] = tile[tx][ty + i];
        }
    } else {
        int e = (bid - 630) * 256 + tid;
        if (e < N_EDGES) atomicAdd(&g_deg[dst[e]], 1);
    }

    // ---- fan-in: last block to finish performs the scan ----
    __threadfence();
    __syncthreads();
    if (tid == 0)
        sflag = (atomicAdd(&g_cnt1, 1) == gridDim.x - 1) ? 1 : 0;
    __syncthreads();
    if (!sflag) return;
    __threadfence();

    int base = tid * 8;
    int v[8];
    int run = 0;
    if (tid < 250) {
        #pragma unroll
        for (int k = 0; k < 8; k++) {
            int d = g_deg[base + k];
            v[k] = run;
            run += d;
        }
    } else {
        #pragma unroll
        for (int k = 0; k < 8; k++) v[k] = 0;
    }
    ssum[tid] = run;
    __syncthreads();
    for (int off = 1; off < 256; off <<= 1) {
        int a = (tid >= off) ? ssum[tid - off] : 0;
        __syncthreads();
        ssum[tid] += a;
        __syncthreads();
    }
    int excl = ssum[tid] - run;
    if (tid < 250) {
        #pragma unroll
        for (int k = 0; k < 8; k++) {
            g_rowptr[base + k] = excl + v[k];
            g_deg[base + k] = 0;
            g_cur[base + k] = 0;
        }
    }
    if (tid == 249) g_rowptr[N_NODES] = excl + run;
    for (int i = tid; i < NG; i += 256) g_S[i] = make_float2(0.0f, 0.0f);
    if (tid == 0) g_cnt1 = 0;
}

// =====================================================================
// K2: fused scatter + CSR-permuted w-transpose.
// =====================================================================
__global__ void __launch_bounds__(NG) scat_wtrans_kernel(
        const float* __restrict__ win,
        const int* __restrict__ src,
        const int* __restrict__ dst) {
    __shared__ float tile[NG][33];           // [g][e], 42.2 KB
    __shared__ int s_pos[32];
    int tid = threadIdx.x;
    int eb = blockIdx.x * 32;

    if (tid < 32) {
        int e = eb + tid;
        int d = dst[e];
        int p = g_rowptr[d] + atomicAdd(&g_cur[d], 1);
        s_pos[tid] = p;
        g_srcc[p] = src[e];
    }

    #pragma unroll
    for (int r = 0; r < 8; r++) {
        int idx = r * NG + tid;
        int g = idx >> 3, q = idx & 7;
        float4 vv = *(const float4*)&win[(size_t)g * N_EDGES + eb + q * 4];
        tile[g][q * 4 + 0] = vv.x;
        tile[g][q * 4 + 1] = vv.y;
        tile[g][q * 4 + 2] = vv.z;
        tile[g][q * 4 + 3] = vv.w;
    }
    __syncthreads();

    #pragma unroll 8
    for (int e = 0; e < 32; e++) {
        g_wT[(size_t)s_pos[e] * NG + tid] = tile[tid][e];
    }
}

// =====================================================================
// K3: GAT reduction (blocks 0..499)  +  head composition (block 500).
//   Block 500 computes M = fcc_w @ fc_w [20x24] and bias2 — runs in
//   parallel with the gat blocks; consumed by K4 next launch.
// =====================================================================
__global__ void __launch_bounds__(NG) gat_kernel(const float* __restrict__ W_node,
                           const float* __restrict__ W_edge,
                           const float* __restrict__ attn_l,
                           const float* __restrict__ attn_e,
                           const float* __restrict__ attn_r,
                           const float* __restrict__ fc_w,
                           const float* __restrict__ fc_b,
                           const float* __restrict__ fcc_w,
                           const float* __restrict__ fcc_b) {
    int g = threadIdx.x;                     // graph 0..319 (or worker id)

    if (blockIdx.x == N_NODES / STRIP) {
        // ---- head composition ----
        __shared__ float s_fcw[160 * HID];   // 15 KB
        for (int i = g; i < 160 * HID; i += NG) s_fcw[i] = fc_w[i];
        __syncthreads();
        for (int idx = g; idx < 20 * HID; idx += NG) {
            int m = idx / HID, k = idx % HID;
            float acc = 0.f;
            #pragma unroll 8
            for (int q = 0; q < 160; q++)
                acc = fmaf(fcc_w[m * 160 + q], s_fcw[q * HID + k], acc);
            g_M[idx] = acc;
        }
        if (g < 20) {
            float acc = fcc_b[g];
            #pragma unroll 8
            for (int q = 0; q < 160; q++)
                acc = fmaf(fcc_w[g * 160 + q], fc_b[q], acc);
            g_bias2[g] = acc;
        }
        return;
    }

    float cL = 0.f, cE = 0.f, cR = 0.f;
    #pragma unroll
    for (int o = 0; o < OUTF; o++) {
        float wn = __ldg(&W_node[o]);
        float we = __ldg(&W_edge[o]);
        cL = fmaf(wn, __ldg(&attn_l[o]), cL);
        cR = fmaf(wn, __ldg(&attn_r[o]), cR);
        cE = fmaf(we, __ldg(&attn_e[o]), cE);
    }

    int n0 = blockIdx.x * STRIP;
    float acc1 = 0.f, acc2 = 0.f;

    #pragma unroll
    for (int nn = 0; nn < STRIP; nn++) {
        int node = n0 + nn;
        float xd = g_xT[(size_t)node * NG + g];
        float based = cR * xd;
        int s0 = g_rowptr[node], s1 = g_rowptr[node + 1];

        float den = 0.f, T1 = 0.f, T2 = 0.f;
        int j = s0;
        for (; j + 4 <= s1; j += 4) {
            int sa = g_srcc[j];
            int sb = g_srcc[j + 1];
            int sc = g_srcc[j + 2];
            int sd = g_srcc[j + 3];
            float w0 = g_wT[(size_t)(j    ) * NG + g];
            float w1 = g_wT[(size_t)(j + 1) * NG + g];
            float w2 = g_wT[(size_t)(j + 2) * NG + g];
            float w3 = g_wT[(size_t)(j + 3) * NG + g];
            float x0 = g_xT[(size_t)sa * NG + g];
            float x1 = g_xT[(size_t)sb * NG + g];
            float x2 = g_xT[(size_t)sc * NG + g];
            float x3 = g_xT[(size_t)sd * NG + g];

            float v0 = fmaf(cL, x0, fmaf(cE, w0, based));
            float v1 = fmaf(cL, x1, fmaf(cE, w1, based));
            float v2 = fmaf(cL, x2, fmaf(cE, w2, based));
            float v3 = fmaf(cL, x3, fmaf(cE, w3, based));
            v0 = fmaxf(v0, NEG_SLOPE * v0);
            v1 = fmaxf(v1, NEG_SLOPE * v1);
            v2 = fmaxf(v2, NEG_SLOPE * v2);
            v3 = fmaxf(v3, NEG_SLOPE * v3);
            float p0 = __expf(v0);
            float p1 = __expf(v1);
            float p2 = __expf(v2);
            float p3 = __expf(v3);
            den += p0; T1 = fmaf(p0, x0, T1); T2 = fmaf(p0, w0, T2);
            den += p1; T1 = fmaf(p1, x1, T1); T2 = fmaf(p1, w1, T2);
            den += p2; T1 = fmaf(p2, x2, T1); T2 = fmaf(p2, w2, T2);
            den += p3; T1 = fmaf(p3, x3, T1); T2 = fmaf(p3, w3, T2);
        }
        for (; j < s1; j++) {
            float w  = g_wT[(size_t)j * NG + g];
            float xs = g_xT[(size_t)g_srcc[j] * NG + g];
            float v = fmaf(cL, xs, fmaf(cE, w, based));
            v = fmaxf(v, NEG_SLOPE * v);
            float p = __expf(v);
            den += p; T1 = fmaf(p, xs, T1); T2 = fmaf(p, w, T2);
        }
        if (s1 > s0) {
            float inv = 1.0f / den;
            acc1 = fmaf(T1, inv, acc1);
            acc2 = fmaf(T2, inv, acc2);
        }
    }
    atomicAdd(&g_S[g].x, acc1);
    atomicAdd(&g_S[g].y, acc2);
}

// =====================================================================
// K4: warp-synchronous LSTM + composed head. 16 CTAs x 32 threads;
//   warp = batch element; lane j<24 owns hidden unit j (h,c,w_hh rows in
//   registers); h broadcast via shuffles feeds BOTH next-step gates and
//   the M-row output dot. Zero block barriers, zero shared memory.
// =====================================================================
__device__ __forceinline__ float sigm(float x) { return 1.0f / (1.0f + __expf(-x)); }
__device__ __forceinline__ float tanhfast(float x) {
    float t = __expf(-2.0f * x);
    return __fdividef(1.0f - t, 1.0f + t);
}

__global__ void __launch_bounds__(32) lstm_head_kernel(
        const float* __restrict__ W_node,
        const float* __restrict__ W_edge,
        const float* __restrict__ gat_b,
        const float* __restrict__ w_ih,
        const float* __restrict__ w_hh,
        const float* __restrict__ b_ih,
        const float* __restrict__ b_hh,
        float* __restrict__ out) {
    int b = blockIdx.x;          // batch 0..15
    int lane = threadIdx.x;      // 0..31
    const float invN = 1.0f / N_NODES;

    // preload all timestep sums (lane t holds step t's pair)
    float s1 = 0.f, s2 = 0.f;
    if (lane < TT) { float2 S = g_S[b * TT + lane]; s1 = S.x; s2 = S.y; }

    // per-gate folded input coefficients + w_hh rows (lane j<24, gates i,f,g,o)
    float A1[4], A2[4], A3[4];
    float whh[4][HID];
    #pragma unroll
    for (int gg = 0; gg < 4; gg++) {
        A1[gg] = A2[gg] = A3[gg] = 0.f;
        #pragma unroll
        for (int j = 0; j < HID; j++) whh[gg][j] = 0.f;
    }
    if (lane < HID) {
        #pragma unroll
        for (int gg = 0; gg < 4; gg++) {
            int row = gg * HID + lane;
            float a1 = 0.f, a2 = 0.f, a3 = b_ih[row] + b_hh[row];
            #pragma unroll
            for (int o = 0; o < OUTF; o++) {
                float wv = w_ih[row * OUTF + o];
                a1 = fmaf(wv, W_node[o], a1);
                a2 = fmaf(wv, W_edge[o], a2);
                a3 = fmaf(wv, gat_b[o], a3);
            }
            A1[gg] = a1 * invN;
            A2[gg] = a2 * invN;
            A3[gg] = a3;
            #pragma unroll
            for (int j = 0; j < HID; j++) whh[gg][j] = w_hh[row * HID + j];
        }
    }

    // composed head row for this lane (lane m<20 -> out column m)
    float Mrow[HID];
    #pragma unroll
    for (int j = 0; j < HID; j++) Mrow[j] = 0.f;
    float bias2 = 0.f;
    if (lane < 20) {
        #pragma unroll
        for (int j = 0; j < HID; j++) Mrow[j] = g_M[lane * HID + j];
        bias2 = g_bias2[lane];
    }

    float h = 0.f, c = 0.f, oacc = 0.f;
    for (int t = 0; t < TT; t++) {
        float S1t = __shfl_sync(0xffffffffu, s1, t);
        float S2t = __shfl_sync(0xffffffffu, s2, t);
        float g0 = fmaf(S1t, A1[0], fmaf(S2t, A2[0], A3[0]));
        float g1 = fmaf(S1t, A1[1], fmaf(S2t, A2[1], A3[1]));
        float g2 = fmaf(S1t, A1[2], fmaf(S2t, A2[2], A3[2]));
        float g3 = fmaf(S1t, A1[3], fmaf(S2t, A2[3], A3[3]));
        if (t > 0) {
            // broadcast h_{t-1}: feeds gates of step t AND output of step t-1
            #pragma unroll
            for (int j = 0; j < HID; j++) {
                float hj = __shfl_sync(0xffffffffu, h, j);
                g0 = fmaf(whh[0][j], hj, g0);
                g1 = fmaf(whh[1][j], hj, g1);
                g2 = fmaf(whh[2][j], hj, g2);
                g3 = fmaf(whh[3][j], hj, g3);
                oacc = fmaf(Mrow[j], hj, oacc);
            }
            if (lane < 20) out[(b * TT + (t - 1)) * 20 + lane] = oacc + bias2;
            oacc = 0.f;
        }
        float gi = sigm(g0);
        float gf = sigm(g1);
        float tg = tanhfast(g2);
        float go = sigm(g3);
        c = fmaf(gf, c, gi * tg);
        h = go * tanhfast(c);
    }
    // final output (step TT-1)
    #pragma unroll
    for (int j = 0; j < HID; j++) {
        float hj = __shfl_sync(0xffffffffu, h, j);
        oacc = fmaf(Mrow[j], hj, oacc);
    }
    if (lane < 20) out[(b * TT + TT - 1) * 20 + lane] = oacc + bias2;
}

// ---------------- launch ----------------
extern "C" void kernel_launch(void* const* d_in, const int* in_sizes, int n_in,
                              void* d_out, int out_size) {
    const float* x      = (const float*)d_in[0];
    const float* ew     = (const float*)d_in[1];
    const int*   src    = (const int*)  d_in[2];
    const int*   dst    = (const int*)  d_in[3];
    const float* W_node = (const float*)d_in[4];
    const float* W_edge = (const float*)d_in[5];
    const float* attn_l = (const float*)d_in[6];
    const float* attn_e = (const float*)d_in[7];
    const float* attn_r = (const float*)d_in[8];
    const float* gat_b  = (const float*)d_in[9];
    const float* w_ih   = (const float*)d_in[10];
    const float* w_hh   = (const float*)d_in[11];
    const float* b_ih   = (const float*)d_in[12];
    const float* b_hh   = (const float*)d_in[13];
    const float* fc_w   = (const float*)d_in[14];
    const float* fc_b   = (const float*)d_in[15];
    const float* fcc_w  = (const float*)d_in[16];
    const float* fcc_b  = (const float*)d_in[17];
    float* out = (float*)d_out;

    xtrans_hist_scan_kernel<<<755, 256>>>(x, dst);
    scat_wtrans_kernel<<<N_EDGES / 32, NG>>>(ew, src, dst);
    gat_kernel<<<N_NODES / STRIP + 1, NG>>>(W_node, W_edge, attn_l, attn_e, attn_r,
                                            fc_w, fc_b, fcc_w, fcc_b);
    lstm_head_kernel<<<BB, 32>>>(W_node, W_edge, gat_b, w_ih, w_hh, b_ih, b_hh, out);
}

// round 8
// speedup vs baseline: 2.7659x; 1.0036x over previous
#include <cuda_runtime.h>
#include <cuda_fp16.h>

#define N_NODES 2000
#define N_EDGES 32000
#define NG      320      // B*T graphs
#define OUTF    8
#define HID     24
#define BB      16
#define TT      20
#define STRIP   4
#define NEG_SLOPE 0.2f

// ---------------- scratch (device globals; no allocs allowed) ----------------
__device__ __half  g_wTh[(size_t)N_EDGES * NG]; // [csr_pos][320]  CSR-ordered, fp16
__device__ float   g_xT[(size_t)N_NODES * NG];  // [node][320]
__device__ int     g_srcc[N_EDGES];             // CSR slot -> src node
__device__ int     g_rowptr[N_NODES + 1];
__device__ int     g_deg[N_NODES];              // zeroed by K1 scan-block each call
__device__ int     g_cur[N_NODES];              // zeroed by K1 scan-block each call
__device__ float2  g_S[NG];                     // zeroed by K1 scan-block each call
__device__ unsigned int g_cnt1 = 0;             // K1 fan-in counter
__device__ float   g_M[20 * HID];               // composed head: fcc_w @ fc_w [20][24]
__device__ float   g_bias2[20];                 // fcc_w @ fc_b + fcc_b

// =====================================================================
// K1: x-transpose [320][N] -> [N][320]  +  degree histogram;
//     LAST block (fan-in) does: scan deg->rowptr, zero deg/cur/S, reset cnt.
// =====================================================================
__global__ void xtrans_hist_scan_kernel(const float* __restrict__ xin,
                                        const int* __restrict__ dst) {
    __shared__ float tile[32][33];
    __shared__ int ssum[256];
    __shared__ int sflag;
    int bid = blockIdx.x;
    int tid = threadIdx.x;

    if (bid < 630) {
        int tx = tid & 31, ty = tid >> 5;
        int cb = (bid % 63) * 32;            // node base
        int rb = (bid / 63) * 32;            // graph base
        #pragma unroll
        for (int i = 0; i < 32; i += 8) {
            int c = cb + tx;
            tile[ty + i][tx] = (c < N_NODES)
                ? xin[(size_t)(rb + ty + i) * N_NODES + c] : 0.0f;
        }
        __syncthreads();
        #pragma unroll
        for (int i = 0; i < 32; i += 8) {
            int c = cb + ty + i;
            if (c < N_NODES) g_xT[(size_t)c * NG + rb + tx] = tile[tx][ty + i];
        }
    } else {
        int e = (bid - 630) * 256 + tid;
        if (e < N_EDGES) atomicAdd(&g_deg[dst[e]], 1);
    }

    __threadfence();
    __syncthreads();
    if (tid == 0)
        sflag = (atomicAdd(&g_cnt1, 1) == gridDim.x - 1) ? 1 : 0;
    __syncthreads();
    if (!sflag) return;
    __threadfence();

    int base = tid * 8;
    int v[8];
    int run = 0;
    if (tid < 250) {
        #pragma unroll
        for (int k = 0; k < 8; k++) {
            int d = g_deg[base + k];
            v[k] = run;
            run += d;
        }
    } else {
        #pragma unroll
        for (int k = 0; k < 8; k++) v[k] = 0;
    }
    ssum[tid] = run;
    __syncthreads();
    for (int off = 1; off < 256; off <<= 1) {
        int a = (tid >= off) ? ssum[tid - off] : 0;
        __syncthreads();
        ssum[tid] += a;
        __syncthreads();
    }
    int excl = ssum[tid] - run;
    if (tid < 250) {
        #pragma unroll
        for (int k = 0; k < 8; k++) {
            g_rowptr[base + k] = excl + v[k];
            g_deg[base + k] = 0;
            g_cur[base + k] = 0;
        }
    }
    if (tid == 249) g_rowptr[N_NODES] = excl + run;
    for (int i = tid; i < NG; i += 256) g_S[i] = make_float2(0.0f, 0.0f);
    if (tid == 0) g_cnt1 = 0;
}

// =====================================================================
// K2: fused scatter + CSR-permuted w-transpose (fp16 output).
// =====================================================================
__global__ void __launch_bounds__(NG) scat_wtrans_kernel(
        const float* __restrict__ win,
        const int* __restrict__ src,
        const int* __restrict__ dst) {
    __shared__ float tile[NG][33];           // [g][e], 42.2 KB
    __shared__ int s_pos[32];
    int tid = threadIdx.x;
    int eb = blockIdx.x * 32;

    if (tid < 32) {
        int e = eb + tid;
        int d = dst[e];
        int p = g_rowptr[d] + atomicAdd(&g_cur[d], 1);
        s_pos[tid] = p;
        g_srcc[p] = src[e];
    }

    #pragma unroll
    for (int r = 0; r < 8; r++) {
        int idx = r * NG + tid;
        int g = idx >> 3, q = idx & 7;
        float4 vv = *(const float4*)&win[(size_t)g * N_EDGES + eb + q * 4];
        tile[g][q * 4 + 0] = vv.x;
        tile[g][q * 4 + 1] = vv.y;
        tile[g][q * 4 + 2] = vv.z;
        tile[g][q * 4 + 3] = vv.w;
    }
    __syncthreads();

    #pragma unroll 8
    for (int e = 0; e < 32; e++) {
        g_wTh[(size_t)s_pos[e] * NG + tid] = __float2half_rn(tile[tid][e]);
    }
}

// =====================================================================
// K3: GAT reduction (blocks 0..499)  +  head composition (block 500).
// =====================================================================
__global__ void __launch_bounds__(NG) gat_kernel(const float* __restrict__ W_node,
                           const float* __restrict__ W_edge,
                           const float* __restrict__ attn_l,
                           const float* __restrict__ attn_e,
                           const float* __restrict__ attn_r,
                           const float* __restrict__ fc_w,
                           const float* __restrict__ fc_b,
                           const float* __restrict__ fcc_w,
                           const float* __restrict__ fcc_b) {
    int g = threadIdx.x;

    if (blockIdx.x == N_NODES / STRIP) {
        __shared__ float s_fcw[160 * HID];   // 15 KB
        for (int i = g; i < 160 * HID; i += NG) s_fcw[i] = fc_w[i];
        __syncthreads();
        for (int idx = g; idx < 20 * HID; idx += NG) {
            int m = idx / HID, k = idx % HID;
            float acc = 0.f;
            #pragma unroll 8
            for (int q = 0; q < 160; q++)
                acc = fmaf(fcc_w[m * 160 + q], s_fcw[q * HID + k], acc);
            g_M[idx] = acc;
        }
        if (g < 20) {
            float acc = fcc_b[g];
            #pragma unroll 8
            for (int q = 0; q < 160; q++)
                acc = fmaf(fcc_w[g * 160 + q], fc_b[q], acc);
            g_bias2[g] = acc;
        }
        return;
    }

    float cL = 0.f, cE = 0.f, cR = 0.f;
    #pragma unroll
    for (int o = 0; o < OUTF; o++) {
        float wn = __ldg(&W_node[o]);
        float we = __ldg(&W_edge[o]);
        cL = fmaf(wn, __ldg(&attn_l[o]), cL);
        cR = fmaf(wn, __ldg(&attn_r[o]), cR);
        cE = fmaf(we, __ldg(&attn_e[o]), cE);
    }

    int n0 = blockIdx.x * STRIP;
    float acc1 = 0.f, acc2 = 0.f;

    #pragma unroll
    for (int nn = 0; nn < STRIP; nn++) {
        int node = n0 + nn;
        float xd = g_xT[(size_t)node * NG + g];
        float based = cR * xd;
        int s0 = g_rowptr[node], s1 = g_rowptr[node + 1];

        float den = 0.f, T1 = 0.f, T2 = 0.f;
        int j = s0;
        for (; j + 4 <= s1; j += 4) {
            int sa = g_srcc[j];
            int sb = g_srcc[j + 1];
            int sc = g_srcc[j + 2];
            int sd = g_srcc[j + 3];
            float w0 = __half2float(g_wTh[(size_t)(j    ) * NG + g]);
            float w1 = __half2float(g_wTh[(size_t)(j + 1) * NG + g]);
            float w2 = __half2float(g_wTh[(size_t)(j + 2) * NG + g]);
            float w3 = __half2float(g_wTh[(size_t)(j + 3) * NG + g]);
            float x0 = g_xT[(size_t)sa * NG + g];
            float x1 = g_xT[(size_t)sb * NG + g];
            float x2 = g_xT[(size_t)sc * NG + g];
            float x3 = g_xT[(size_t)sd * NG + g];

            float v0 = fmaf(cL, x0, fmaf(cE, w0, based));
            float v1 = fmaf(cL, x1, fmaf(cE, w1, based));
            float v2 = fmaf(cL, x2, fmaf(cE, w2, based));
            float v3 = fmaf(cL, x3, fmaf(cE, w3, based));
            v0 = fmaxf(v0, NEG_SLOPE * v0);
            v1 = fmaxf(v1, NEG_SLOPE * v1);
            v2 = fmaxf(v2, NEG_SLOPE * v2);
            v3 = fmaxf(v3, NEG_SLOPE * v3);
            float p0 = __expf(v0);
            float p1 = __expf(v1);
            float p2 = __expf(v2);
            float p3 = __expf(v3);
            den += p0; T1 = fmaf(p0, x0, T1); T2 = fmaf(p0, w0, T2);
            den += p1; T1 = fmaf(p1, x1, T1); T2 = fmaf(p1, w1, T2);
            den += p2; T1 = fmaf(p2, x2, T1); T2 = fmaf(p2, w2, T2);
            den += p3; T1 = fmaf(p3, x3, T1); T2 = fmaf(p3, w3, T2);
        }
        for (; j < s1; j++) {
            float w  = __half2float(g_wTh[(size_t)j * NG + g]);
            float xs = g_xT[(size_t)g_srcc[j] * NG + g];
            float v = fmaf(cL, xs, fmaf(cE, w, based));
            v = fmaxf(v, NEG_SLOPE * v);
            float p = __expf(v);
            den += p; T1 = fmaf(p, xs, T1); T2 = fmaf(p, w, T2);
        }
        if (s1 > s0) {
            float inv = 1.0f / den;
            acc1 = fmaf(T1, inv, acc1);
            acc2 = fmaf(T2, inv, acc2);
        }
    }
    atomicAdd(&g_S[g].x, acc1);
    atomicAdd(&g_S[g].y, acc2);
}

// =====================================================================
// K4: warp-synchronous LSTM + composed head.
//   16 CTAs x 32 threads; warp = batch element. All weight preloads go
//   through smem with COALESCED warp loads (fixes the 3000-cyc wavefront
//   storm of per-lane strided LDGs), then per-lane register copies.
//   2-way split accumulator chains halve the per-step FMA chain latency.
// =====================================================================
__device__ __forceinline__ float sigm(float x) { return 1.0f / (1.0f + __expf(-x)); }
__device__ __forceinline__ float tanhfast(float x) {
    float t = __expf(-2.0f * x);
    return __fdividef(1.0f - t, 1.0f + t);
}

__global__ void __launch_bounds__(32) lstm_head_kernel(
        const float* __restrict__ W_node,
        const float* __restrict__ W_edge,
        const float* __restrict__ gat_b,
        const float* __restrict__ w_ih,
        const float* __restrict__ w_hh,
        const float* __restrict__ b_ih,
        const float* __restrict__ b_hh,
        float* __restrict__ out) {
    int b = blockIdx.x;          // batch 0..15
    int lane = threadIdx.x;      // 0..31
    const float invN = 1.0f / N_NODES;

    __shared__ float s_whh[4 * HID * HID];   // 2304 floats
    __shared__ float s_wih[4 * HID * OUTF];  // 768
    __shared__ float s_M[20 * HID];          // 480

    // coalesced staging loads
    for (int i = lane; i < 4 * HID * HID; i += 32) s_whh[i] = w_hh[i];
    for (int i = lane; i < 4 * HID * OUTF; i += 32) s_wih[i] = w_ih[i];
    for (int i = lane; i < 20 * HID; i += 32) s_M[i] = g_M[i];
    __syncwarp();

    // preload timestep sums (lane t holds step t's pair)
    float s1 = 0.f, s2 = 0.f;
    if (lane < TT) { float2 S = g_S[b * TT + lane]; s1 = S.x; s2 = S.y; }

    int ln = (lane < HID) ? lane : HID - 1;      // clamp: keep warp converged
    int lm = (lane < 20) ? lane : 19;

    // folded input coefficients + w_hh rows in registers (from smem)
    float A1[4], A2[4], A3[4];
    float whh[4][HID];
    #pragma unroll
    for (int gg = 0; gg < 4; gg++) {
        int row = gg * HID + ln;
        float a1 = 0.f, a2 = 0.f, a3 = b_ih[row] + b_hh[row];
        #pragma unroll
        for (int o = 0; o < OUTF; o++) {
            float wv = s_wih[row * OUTF + o];
            a1 = fmaf(wv, W_node[o], a1);
            a2 = fmaf(wv, W_edge[o], a2);
            a3 = fmaf(wv, gat_b[o], a3);
        }
        A1[gg] = a1 * invN;
        A2[gg] = a2 * invN;
        A3[gg] = a3;
        #pragma unroll
        for (int j = 0; j < HID; j++) whh[gg][j] = s_whh[row * HID + j];
    }

    float Mrow[HID];
    #pragma unroll
    for (int j = 0; j < HID; j++) Mrow[j] = s_M[lm * HID + j];
    float bias2 = g_bias2[lm];

    float h = 0.f, c = 0.f;
    for (int t = 0; t < TT; t++) {
        float S1t = __shfl_sync(0xffffffffu, s1, t);
        float S2t = __shfl_sync(0xffffffffu, s2, t);
        float g0a = fmaf(S1t, A1[0], fmaf(S2t, A2[0], A3[0])), g0b = 0.f;
        float g1a = fmaf(S1t, A1[1], fmaf(S2t, A2[1], A3[1])), g1b = 0.f;
        float g2a = fmaf(S1t, A1[2], fmaf(S2t, A2[2], A3[2])), g2b = 0.f;
        float g3a = fmaf(S1t, A1[3], fmaf(S2t, A2[3], A3[3])), g3b = 0.f;
        float oa = 0.f, ob = 0.f;
        if (t > 0) {
            // broadcast h_{t-1}: feeds step-t gates AND step-(t-1) output
            #pragma unroll
            for (int j = 0; j < HID; j += 2) {
                float h0 = __shfl_sync(0xffffffffu, h, j);
                float h1 = __shfl_sync(0xffffffffu, h, j + 1);
                g0a = fmaf(whh[0][j], h0, g0a); g0b = fmaf(whh[0][j + 1], h1, g0b);
                g1a = fmaf(whh[1][j], h0, g1a); g1b = fmaf(whh[1][j + 1], h1, g1b);
                g2a = fmaf(whh[2][j], h0, g2a); g2b = fmaf(whh[2][j + 1], h1, g2b);
                g3a = fmaf(whh[3][j], h0, g3a); g3b = fmaf(whh[3][j + 1], h1, g3b);
                oa  = fmaf(Mrow[j], h0, oa);    ob  = fmaf(Mrow[j + 1], h1, ob);
            }
            if (lane < 20) out[(b * TT + (t - 1)) * 20 + lane] = oa + ob + bias2;
        }
        float gi = sigm(g0a + g0b);
        float gf = sigm(g1a + g1b);
        float tg = tanhfast(g2a + g2b);
        float go = sigm(g3a + g3b);
        c = fmaf(gf, c, gi * tg);
        h = go * tanhfast(c);
    }
    // final output (step TT-1)
    float oa = 0.f, ob = 0.f;
    #pragma unroll
    for (int j = 0; j < HID; j += 2) {
        float h0 = __shfl_sync(0xffffffffu, h, j);
        float h1 = __shfl_sync(0xffffffffu, h, j + 1);
        oa = fmaf(Mrow[j], h0, oa);
        ob = fmaf(Mrow[j + 1], h1, ob);
    }
    if (lane < 20) out[(b * TT + TT - 1) * 20 + lane] = oa + ob + bias2;
}

// ---------------- launch ----------------
extern "C" void kernel_launch(void* const* d_in, const int* in_sizes, int n_in,
                              void* d_out, int out_size) {
    const float* x      = (const float*)d_in[0];
    const float* ew     = (const float*)d_in[1];
    const int*   src    = (const int*)  d_in[2];
    const int*   dst    = (const int*)  d_in[3];
    const float* W_node = (const float*)d_in[4];
    const float* W_edge = (const float*)d_in[5];
    const float* attn_l = (const float*)d_in[6];
    const float* attn_e = (const float*)d_in[7];
    const float* attn_r = (const float*)d_in[8];
    const float* gat_b  = (const float*)d_in[9];
    const float* w_ih   = (const float*)d_in[10];
    const float* w_hh   = (const float*)d_in[11];
    const float* b_ih   = (const float*)d_in[12];
    const float* b_hh   = (const float*)d_in[13];
    const float* fc_w   = (const float*)d_in[14];
    const float* fc_b   = (const float*)d_in[15];
    const float* fcc_w  = (const float*)d_in[16];
    const float* fcc_b  = (const float*)d_in[17];
    float* out = (float*)d_out;

    xtrans_hist_scan_kernel<<<755, 256>>>(x, dst);
    scat_wtrans_kernel<<<N_EDGES / 32, NG>>>(ew, src, dst);
    gat_kernel<<<N_NODES / STRIP + 1, NG>>>(W_node, W_edge, attn_l, attn_e, attn_r,
                                            fc_w, fc_b, fcc_w, fcc_b);
    lstm_head_kernel<<<BB, 32>>>(W_node, W_edge, gat_b, w_ih, w_hh, b_ih, b_hh, out);
}

// round 9
// speedup vs baseline: 3.0693x; 1.1097x over previous
#include <cuda_runtime.h>
#include <cuda_fp16.h>

#define N_NODES 2000
#define N_EDGES 32000
#define NG      320      // B*T graphs
#define OUTF    8
#define HID     24
#define BB      16
#define TT      20
#define STRIP   4
#define NEG_SLOPE 0.2f

// ---------------- scratch (device globals; no allocs allowed) ----------------
__device__ __half  g_wTh[(size_t)N_EDGES * NG]; // [csr_pos][320]  CSR-ordered, fp16
__device__ float   g_xT[(size_t)N_NODES * NG];  // [node][320]
__device__ int     g_srcc[N_EDGES];             // CSR slot -> src node
__device__ int     g_rowptr[N_NODES + 1];
__device__ int     g_deg[N_NODES];              // zeroed by K1 scan-block each call
__device__ int     g_cur[N_NODES];              // zeroed by K1 scan-block each call
__device__ float2  g_S[NG];                     // zeroed by K1 scan-block each call
__device__ unsigned int g_cnt1 = 0;             // K1 fan-in counter
__device__ float   g_M[20 * HID];               // composed head: fcc_w @ fc_w [20][24]
__device__ float   g_bias2[20];                 // fcc_w @ fc_b + fcc_b

// =====================================================================
// K1: x-transpose [320][N] -> [N][320]  +  degree histogram;
//     LAST block (fan-in) does: scan deg->rowptr, zero deg/cur/S, reset cnt.
// =====================================================================
__global__ void xtrans_hist_scan_kernel(const float* __restrict__ xin,
                                        const int* __restrict__ dst) {
    __shared__ float tile[32][33];
    __shared__ int ssum[256];
    __shared__ int sflag;
    int bid = blockIdx.x;
    int tid = threadIdx.x;

    if (bid < 630) {
        int tx = tid & 31, ty = tid >> 5;
        int cb = (bid % 63) * 32;            // node base
        int rb = (bid / 63) * 32;            // graph base
        #pragma unroll
        for (int i = 0; i < 32; i += 8) {
            int c = cb + tx;
            tile[ty + i][tx] = (c < N_NODES)
                ? xin[(size_t)(rb + ty + i) * N_NODES + c] : 0.0f;
        }
        __syncthreads();
        #pragma unroll
        for (int i = 0; i < 32; i += 8) {
            int c = cb + ty + i;
            if (c < N_NODES) g_xT[(size_t)c * NG + rb + tx] = tile[tx][ty + i];
        }
    } else {
        int e = (bid - 630) * 256 + tid;
        if (e < N_EDGES) atomicAdd(&g_deg[dst[e]], 1);
    }

    __threadfence();
    __syncthreads();
    if (tid == 0)
        sflag = (atomicAdd(&g_cnt1, 1) == gridDim.x - 1) ? 1 : 0;
    __syncthreads();
    if (!sflag) return;
    __threadfence();

    int base = tid * 8;
    int v[8];
    int run = 0;
    if (tid < 250) {
        #pragma unroll
        for (int k = 0; k < 8; k++) {
            int d = g_deg[base + k];
            v[k] = run;
            run += d;
        }
    } else {
        #pragma unroll
        for (int k = 0; k < 8; k++) v[k] = 0;
    }
    ssum[tid] = run;
    __syncthreads();
    for (int off = 1; off < 256; off <<= 1) {
        int a = (tid >= off) ? ssum[tid - off] : 0;
        __syncthreads();
        ssum[tid] += a;
        __syncthreads();
    }
    int excl = ssum[tid] - run;
    if (tid < 250) {
        #pragma unroll
        for (int k = 0; k < 8; k++) {
            g_rowptr[base + k] = excl + v[k];
            g_deg[base + k] = 0;
            g_cur[base + k] = 0;
        }
    }
    if (tid == 249) g_rowptr[N_NODES] = excl + run;
    for (int i = tid; i < NG; i += 256) g_S[i] = make_float2(0.0f, 0.0f);
    if (tid == 0) g_cnt1 = 0;
}

// =====================================================================
// K2: fused scatter + CSR-permuted w-transpose (fp16 output).
// =====================================================================
__global__ void __launch_bounds__(NG) scat_wtrans_kernel(
        const float* __restrict__ win,
        const int* __restrict__ src,
        const int* __restrict__ dst) {
    __shared__ float tile[NG][33];           // [g][e], 42.2 KB
    __shared__ int s_pos[32];
    int tid = threadIdx.x;
    int eb = blockIdx.x * 32;

    if (tid < 32) {
        int e = eb + tid;
        int d = dst[e];
        int p = g_rowptr[d] + atomicAdd(&g_cur[d], 1);
        s_pos[tid] = p;
        g_srcc[p] = src[e];
    }

    #pragma unroll
    for (int r = 0; r < 8; r++) {
        int idx = r * NG + tid;
        int g = idx >> 3, q = idx & 7;
        float4 vv = *(const float4*)&win[(size_t)g * N_EDGES + eb + q * 4];
        tile[g][q * 4 + 0] = vv.x;
        tile[g][q * 4 + 1] = vv.y;
        tile[g][q * 4 + 2] = vv.z;
        tile[g][q * 4 + 3] = vv.w;
    }
    __syncthreads();

    #pragma unroll 8
    for (int e = 0; e < 32; e++) {
        g_wTh[(size_t)s_pos[e] * NG + tid] = __float2half_rn(tile[tid][e]);
    }
}

// =====================================================================
// K3: GAT reduction (blocks 0..499)  +  head composition (block 500).
// =====================================================================
__global__ void __launch_bounds__(NG) gat_kernel(const float* __restrict__ W_node,
                           const float* __restrict__ W_edge,
                           const float* __restrict__ attn_l,
                           const float* __restrict__ attn_e,
                           const float* __restrict__ attn_r,
                           const float* __restrict__ fc_w,
                           const float* __restrict__ fc_b,
                           const float* __restrict__ fcc_w,
                           const float* __restrict__ fcc_b) {
    int g = threadIdx.x;

    if (blockIdx.x == N_NODES / STRIP) {
        __shared__ float s_fcw[160 * HID];   // 15 KB
        for (int i = g; i < 160 * HID; i += NG) s_fcw[i] = fc_w[i];
        __syncthreads();
        for (int idx = g; idx < 20 * HID; idx += NG) {
            int m = idx / HID, k = idx % HID;
            float acc = 0.f;
            #pragma unroll 8
            for (int q = 0; q < 160; q++)
                acc = fmaf(fcc_w[m * 160 + q], s_fcw[q * HID + k], acc);
            g_M[idx] = acc;
        }
        if (g < 20) {
            float acc = fcc_b[g];
            #pragma unroll 8
            for (int q = 0; q < 160; q++)
                acc = fmaf(fcc_w[g * 160 + q], fc_b[q], acc);
            g_bias2[g] = acc;
        }
        return;
    }

    float cL = 0.f, cE = 0.f, cR = 0.f;
    #pragma unroll
    for (int o = 0; o < OUTF; o++) {
        float wn = __ldg(&W_node[o]);
        float we = __ldg(&W_edge[o]);
        cL = fmaf(wn, __ldg(&attn_l[o]), cL);
        cR = fmaf(wn, __ldg(&attn_r[o]), cR);
        cE = fmaf(we, __ldg(&attn_e[o]), cE);
    }

    int n0 = blockIdx.x * STRIP;
    float acc1 = 0.f, acc2 = 0.f;

    #pragma unroll
    for (int nn = 0; nn < STRIP; nn++) {
        int node = n0 + nn;
        float xd = g_xT[(size_t)node * NG + g];
        float based = cR * xd;
        int s0 = g_rowptr[node], s1 = g_rowptr[node + 1];

        float den = 0.f, T1 = 0.f, T2 = 0.f;
        int j = s0;
        for (; j + 4 <= s1; j += 4) {
            int sa = g_srcc[j];
            int sb = g_srcc[j + 1];
            int sc = g_srcc[j + 2];
            int sd = g_srcc[j + 3];
            float w0 = __half2float(g_wTh[(size_t)(j    ) * NG + g]);
            float w1 = __half2float(g_wTh[(size_t)(j + 1) * NG + g]);
            float w2 = __half2float(g_wTh[(size_t)(j + 2) * NG + g]);
            float w3 = __half2float(g_wTh[(size_t)(j + 3) * NG + g]);
            float x0 = g_xT[(size_t)sa * NG + g];
            float x1 = g_xT[(size_t)sb * NG + g];
            float x2 = g_xT[(size_t)sc * NG + g];
            float x3 = g_xT[(size_t)sd * NG + g];

            float v0 = fmaf(cL, x0, fmaf(cE, w0, based));
            float v1 = fmaf(cL, x1, fmaf(cE, w1, based));
            float v2 = fmaf(cL, x2, fmaf(cE, w2, based));
            float v3 = fmaf(cL, x3, fmaf(cE, w3, based));
            v0 = fmaxf(v0, NEG_SLOPE * v0);
            v1 = fmaxf(v1, NEG_SLOPE * v1);
            v2 = fmaxf(v2, NEG_SLOPE * v2);
            v3 = fmaxf(v3, NEG_SLOPE * v3);
            float p0 = __expf(v0);
            float p1 = __expf(v1);
            float p2 = __expf(v2);
            float p3 = __expf(v3);
            den += p0; T1 = fmaf(p0, x0, T1); T2 = fmaf(p0, w0, T2);
            den += p1; T1 = fmaf(p1, x1, T1); T2 = fmaf(p1, w1, T2);
            den += p2; T1 = fmaf(p2, x2, T1); T2 = fmaf(p2, w2, T2);
            den += p3; T1 = fmaf(p3, x3, T1); T2 = fmaf(p3, w3, T2);
        }
        for (; j < s1; j++) {
            float w  = __half2float(g_wTh[(size_t)j * NG + g]);
            float xs = g_xT[(size_t)g_srcc[j] * NG + g];
            float v = fmaf(cL, xs, fmaf(cE, w, based));
            v = fmaxf(v, NEG_SLOPE * v);
            float p = __expf(v);
            den += p; T1 = fmaf(p, xs, T1); T2 = fmaf(p, w, T2);
        }
        if (s1 > s0) {
            float inv = 1.0f / den;
            acc1 = fmaf(T1, inv, acc1);
            acc2 = fmaf(T2, inv, acc2);
        }
    }
    atomicAdd(&g_S[g].x, acc1);
    atomicAdd(&g_S[g].y, acc2);
}

// =====================================================================
// K4: warp-synchronous LSTM + composed head (exact R7 version, 13.9us).
//   16 CTAs x 32 threads; warp = batch element; lane j<24 owns hidden
//   unit j; h broadcast via shuffles feeds next-step gates AND M-row dot.
// =====================================================================
__device__ __forceinline__ float sigm(float x) { return 1.0f / (1.0f + __expf(-x)); }
__device__ __forceinline__ float tanhfast(float x) {
    float t = __expf(-2.0f * x);
    return __fdividef(1.0f - t, 1.0f + t);
}

__global__ void __launch_bounds__(32) lstm_head_kernel(
        const float* __restrict__ W_node,
        const float* __restrict__ W_edge,
        const float* __restrict__ gat_b,
        const float* __restrict__ w_ih,
        const float* __restrict__ w_hh,
        const float* __restrict__ b_ih,
        const float* __restrict__ b_hh,
        float* __restrict__ out) {
    int b = blockIdx.x;          // batch 0..15
    int lane = threadIdx.x;      // 0..31
    const float invN = 1.0f / N_NODES;

    // preload all timestep sums (lane t holds step t's pair)
    float s1 = 0.f, s2 = 0.f;
    if (lane < TT) { float2 S = g_S[b * TT + lane]; s1 = S.x; s2 = S.y; }

    // per-gate folded input coefficients + w_hh rows (lane j<24, gates i,f,g,o)
    float A1[4], A2[4], A3[4];
    float whh[4][HID];
    #pragma unroll
    for (int gg = 0; gg < 4; gg++) {
        A1[gg] = A2[gg] = A3[gg] = 0.f;
        #pragma unroll
        for (int j = 0; j < HID; j++) whh[gg][j] = 0.f;
    }
    if (lane < HID) {
        #pragma unroll
        for (int gg = 0; gg < 4; gg++) {
            int row = gg * HID + lane;
            float a1 = 0.f, a2 = 0.f, a3 = b_ih[row] + b_hh[row];
            #pragma unroll
            for (int o = 0; o < OUTF; o++) {
                float wv = w_ih[row * OUTF + o];
                a1 = fmaf(wv, W_node[o], a1);
                a2 = fmaf(wv, W_edge[o], a2);
                a3 = fmaf(wv, gat_b[o], a3);
            }
            A1[gg] = a1 * invN;
            A2[gg] = a2 * invN;
            A3[gg] = a3;
            #pragma unroll
            for (int j = 0; j < HID; j++) whh[gg][j] = w_hh[row * HID + j];
        }
    }

    // composed head row for this lane (lane m<20 -> out column m)
    float Mrow[HID];
    #pragma unroll
    for (int j = 0; j < HID; j++) Mrow[j] = 0.f;
    float bias2 = 0.f;
    if (lane < 20) {
        #pragma unroll
        for (int j = 0; j < HID; j++) Mrow[j] = g_M[lane * HID + j];
        bias2 = g_bias2[lane];
    }

    float h = 0.f, c = 0.f, oacc = 0.f;
    for (int t = 0; t < TT; t++) {
        float S1t = __shfl_sync(0xffffffffu, s1, t);
        float S2t = __shfl_sync(0xffffffffu, s2, t);
        float g0 = fmaf(S1t, A1[0], fmaf(S2t, A2[0], A3[0]));
        float g1 = fmaf(S1t, A1[1], fmaf(S2t, A2[1], A3[1]));
        float g2 = fmaf(S1t, A1[2], fmaf(S2t, A2[2], A3[2]));
        float g3 = fmaf(S1t, A1[3], fmaf(S2t, A2[3], A3[3]));
        if (t > 0) {
            // broadcast h_{t-1}: feeds gates of step t AND output of step t-1
            #pragma unroll
            for (int j = 0; j < HID; j++) {
                float hj = __shfl_sync(0xffffffffu, h, j);
                g0 = fmaf(whh[0][j], hj, g0);
                g1 = fmaf(whh[1][j], hj, g1);
                g2 = fmaf(whh[2][j], hj, g2);
                g3 = fmaf(whh[3][j], hj, g3);
                oacc = fmaf(Mrow[j], hj, oacc);
            }
            if (lane < 20) out[(b * TT + (t - 1)) * 20 + lane] = oacc + bias2;
            oacc = 0.f;
        }
        float gi = sigm(g0);
        float gf = sigm(g1);
        float tg = tanhfast(g2);
        float go = sigm(g3);
        c = fmaf(gf, c, gi * tg);
        h = go * tanhfast(c);
    }
    // final output (step TT-1)
    #pragma unroll
    for (int j = 0; j < HID; j++) {
        float hj = __shfl_sync(0xffffffffu, h, j);
        oacc = fmaf(Mrow[j], hj, oacc);
    }
    if (lane < 20) out[(b * TT + TT - 1) * 20 + lane] = oacc + bias2;
}

// ---------------- launch ----------------
extern "C" void kernel_launch(void* const* d_in, const int* in_sizes, int n_in,
                              void* d_out, int out_size) {
    const float* x      = (const float*)d_in[0];
    const float* ew     = (const float*)d_in[1];
    const int*   src    = (const int*)  d_in[2];
    const int*   dst    = (const int*)  d_in[3];
    const float* W_node = (const float*)d_in[4];
    const float* W_edge = (const float*)d_in[5];
    const float* attn_l = (const float*)d_in[6];
    const float* attn_e = (const float*)d_in[7];
    const float* attn_r = (const float*)d_in[8];
    const float* gat_b  = (const float*)d_in[9];
    const float* w_ih   = (const float*)d_in[10];
    const float* w_hh   = (const float*)d_in[11];
    const float* b_ih   = (const float*)d_in[12];
    const float* b_hh   = (const float*)d_in[13];
    const float* fc_w   = (const float*)d_in[14];
    const float* fc_b   = (const float*)d_in[15];
    const float* fcc_w  = (const float*)d_in[16];
    const float* fcc_b  = (const float*)d_in[17];
    float* out = (float*)d_out;

    xtrans_hist_scan_kernel<<<755, 256>>>(x, dst);
    scat_wtrans_kernel<<<N_EDGES / 32, NG>>>(ew, src, dst);
    gat_kernel<<<N_NODES / STRIP + 1, NG>>>(W_node, W_edge, attn_l, attn_e, attn_r,
                                            fc_w, fc_b, fcc_w, fcc_b);
    lstm_head_kernel<<<BB, 32>>>(W_node, W_edge, gat_b, w_ih, w_hh, b_ih, b_hh, out);
}